// round 1
// baseline (speedup 1.0000x reference)
#include <cuda_runtime.h>

#define LL 4096
#define DM 384
#define DI 768
#define DS 16
#define DR 24
#define NB 2
#define XW (DR + 2*DS)   // 56

// ----------------------------- scratch (device globals) -----------------------------
__device__ float g_xz   [2][NB][LL][2*DI];   // in-proj output: [0..767]=xi, [768..1535]=z
__device__ float g_xc   [2][NB][LL][DI];     // after causal conv + silu
__device__ float g_xdbl [2][NB][LL][XW];     // x-proj output (dt | B | C)
__device__ float g_delta[2][NB][LL][DI];     // softplus(dt@dtw+b); later reused as gate output
__device__ float g_du   [2][NB][LL][DI];     // delta * xc
__device__ float g_Bc   [2][NB][LL/4][DS][4];// B repacked [t/4][n][t%4]
__device__ float g_Cc   [2][NB][LL/4][DS][4];
__device__ float g_y    [2][NB][LL][DI];     // scan output
__device__ float g_ycat [NB][LL][2*DM];      // concat(yf, yb) rows (b,t)
__device__ float g_yc   [NB][LL][2*DM];      // after final 1x1 conv + bias
__device__ float g_glu  [NB][LL][DM];        // a * sigmoid(b)
__device__ float2 g_part[NB][64];
__device__ float2 g_stats[NB];

// ----------------------------- f32x2 helpers -----------------------------
__device__ __forceinline__ unsigned long long dup2(float x){
    unsigned long long r; asm("mov.b64 %0, {%1, %1};" : "=l"(r) : "f"(x)); return r;
}
__device__ __forceinline__ void ffma2(unsigned long long &d, unsigned long long a, unsigned long long b){
    asm("fma.rn.f32x2 %0, %1, %2, %0;" : "+l"(d) : "l"(a), "l"(b));
}
__device__ __forceinline__ float2 unpk2(unsigned long long v){
    float2 f; asm("mov.b64 {%0, %1}, %2;" : "=f"(f.x), "=f"(f.y) : "l"(v)); return f;
}

// ----------------------------- GEMM: in-proj (A = x "transposed", per dir/batch) -----------------------------
// C[dir][b][t][n] = sum_k x[b][k][ts(t)] * W_dir[n][k],  ts = t (fwd) or L-1-t (bwd)
__global__ __launch_bounds__(256) void gemm_inproj(
    const float* __restrict__ x,
    const float* __restrict__ W0, const float* __restrict__ W1)
{
    __shared__ float As[16][64];
    __shared__ float Bs[16][64];
    const int z = blockIdx.z;            // dir*2 + b
    const int dir = z >> 1, b = z & 1;
    const float* W  = dir ? W1 : W0;
    const float* xb = x + (long)b * DM * LL;
    float* Cb = &g_xz[dir][b][0][0];
    const int row0 = blockIdx.y * 64;    // t tile
    const int col0 = blockIdx.x * 64;    // n tile
    const int tid = threadIdx.x;
    const int tx = tid & 15, ty = tid >> 4;

    const int am = tid & 63;             // A loader: t within tile
    const int akq = tid >> 6;            // 0..3
    const int wn = tid >> 2;             // W loader: n within tile
    const int wk4 = (tid & 3) * 4;

    unsigned long long acc[2][4];
    #pragma unroll
    for (int i = 0; i < 2; i++)
        #pragma unroll
        for (int j = 0; j < 4; j++) acc[i][j] = 0ull;

    const int t = row0 + am;
    const int ts = dir ? (LL - 1 - t) : t;

    for (int k0 = 0; k0 < DM; k0 += 16) {
        #pragma unroll
        for (int i = 0; i < 4; i++) {
            int k = akq * 4 + i;
            As[k][am] = xb[(long)(k0 + k) * LL + ts];
        }
        {
            float4 v = *(const float4*)&W[(long)(col0 + wn) * DM + k0 + wk4];
            Bs[wk4+0][wn] = v.x; Bs[wk4+1][wn] = v.y; Bs[wk4+2][wn] = v.z; Bs[wk4+3][wn] = v.w;
        }
        __syncthreads();
        #pragma unroll
        for (int k = 0; k < 16; k++) {
            unsigned long long a01 = *(const unsigned long long*)&As[k][ty*4];
            unsigned long long a23 = *(const unsigned long long*)&As[k][ty*4+2];
            float4 bv = *(const float4*)&Bs[k][tx*4];
            unsigned long long b0 = dup2(bv.x), b1 = dup2(bv.y), b2 = dup2(bv.z), b3 = dup2(bv.w);
            ffma2(acc[0][0], a01, b0); ffma2(acc[0][1], a01, b1);
            ffma2(acc[0][2], a01, b2); ffma2(acc[0][3], a01, b3);
            ffma2(acc[1][0], a23, b0); ffma2(acc[1][1], a23, b1);
            ffma2(acc[1][2], a23, b2); ffma2(acc[1][3], a23, b3);
        }
        __syncthreads();
    }
    float out[4][4];
    #pragma unroll
    for (int i = 0; i < 2; i++)
        #pragma unroll
        for (int j = 0; j < 4; j++) {
            float2 f = unpk2(acc[i][j]);
            out[2*i][j] = f.x; out[2*i+1][j] = f.y;
        }
    const int colb = col0 + tx*4;
    #pragma unroll
    for (int r = 0; r < 4; r++) {
        long off = (long)(row0 + ty*4 + r) * (2*DI) + colb;
        float4 v = make_float4(out[r][0], out[r][1], out[r][2], out[r][3]);
        *(float4*)&Cb[off] = v;
    }
}

// ----------------------------- GEMM: generic row-major A, W[N][K], opt bias -----------------------------
__global__ __launch_bounds__(256) void gemm_generic(
    const float* __restrict__ A, int lda, long Az,
    const float* __restrict__ W0, const float* __restrict__ W1,
    const float* __restrict__ bias,
    float* __restrict__ C, int ldc, long Cz,
    int N, int K)
{
    __shared__ float As[16][64];
    __shared__ float Bs[16][64];
    const int z = blockIdx.z;
    const float* Ab = A + (long)z * Az;
    const float* W  = (z == 0) ? W0 : W1;
    float* Cb = C + (long)z * Cz;
    const int row0 = blockIdx.y * 64;
    const int col0 = blockIdx.x * 64;
    const int tid = threadIdx.x;
    const int tx = tid & 15, ty = tid >> 4;
    const int lm = tid >> 2;
    const int lk4 = (tid & 3) * 4;

    unsigned long long acc[2][4];
    #pragma unroll
    for (int i = 0; i < 2; i++)
        #pragma unroll
        for (int j = 0; j < 4; j++) acc[i][j] = 0ull;

    for (int k0 = 0; k0 < K; k0 += 16) {
        {
            float4 v = *(const float4*)&Ab[(long)(row0 + lm) * lda + k0 + lk4];
            As[lk4+0][lm] = v.x; As[lk4+1][lm] = v.y; As[lk4+2][lm] = v.z; As[lk4+3][lm] = v.w;
        }
        {
            float4 v = make_float4(0.f, 0.f, 0.f, 0.f);
            if (col0 + lm < N) v = *(const float4*)&W[(long)(col0 + lm) * K + k0 + lk4];
            Bs[lk4+0][lm] = v.x; Bs[lk4+1][lm] = v.y; Bs[lk4+2][lm] = v.z; Bs[lk4+3][lm] = v.w;
        }
        __syncthreads();
        #pragma unroll
        for (int k = 0; k < 16; k++) {
            unsigned long long a01 = *(const unsigned long long*)&As[k][ty*4];
            unsigned long long a23 = *(const unsigned long long*)&As[k][ty*4+2];
            float4 bv = *(const float4*)&Bs[k][tx*4];
            unsigned long long b0 = dup2(bv.x), b1 = dup2(bv.y), b2 = dup2(bv.z), b3 = dup2(bv.w);
            ffma2(acc[0][0], a01, b0); ffma2(acc[0][1], a01, b1);
            ffma2(acc[0][2], a01, b2); ffma2(acc[0][3], a01, b3);
            ffma2(acc[1][0], a23, b0); ffma2(acc[1][1], a23, b1);
            ffma2(acc[1][2], a23, b2); ffma2(acc[1][3], a23, b3);
        }
        __syncthreads();
    }
    float out[4][4];
    #pragma unroll
    for (int i = 0; i < 2; i++)
        #pragma unroll
        for (int j = 0; j < 4; j++) {
            float2 f = unpk2(acc[i][j]);
            out[2*i][j] = f.x; out[2*i+1][j] = f.y;
        }
    const int colb = col0 + tx*4;
    float bsv[4] = {0.f, 0.f, 0.f, 0.f};
    if (bias) {
        #pragma unroll
        for (int j = 0; j < 4; j++) if (colb + j < N) bsv[j] = bias[colb + j];
    }
    #pragma unroll
    for (int r = 0; r < 4; r++) {
        long off = (long)(row0 + ty*4 + r) * ldc;
        if (colb + 3 < N) {
            float4 v = make_float4(out[r][0]+bsv[0], out[r][1]+bsv[1], out[r][2]+bsv[2], out[r][3]+bsv[3]);
            *(float4*)&Cb[off + colb] = v;
        } else {
            #pragma unroll
            for (int j = 0; j < 4; j++)
                if (colb + j < N) Cb[off + colb + j] = out[r][j] + bsv[j];
        }
    }
}

// ----------------------------- depthwise causal conv + silu -----------------------------
__global__ __launch_bounds__(256) void conv_silu_kernel(
    const float* __restrict__ cw0, const float* __restrict__ cb0,
    const float* __restrict__ cw1, const float* __restrict__ cb1)
{
    long id = (long)blockIdx.x * 256 + threadIdx.x;
    const long total = (long)2 * NB * LL * DI;
    if (id >= total) return;
    int d = (int)(id % DI); long r = id / DI;
    int t = (int)(r % LL); r /= LL;
    int b = (int)(r % NB); int dir = (int)(r / NB);
    const float* cw = dir ? cw1 : cw0;
    const float* cb = dir ? cb1 : cb0;
    const float* xi = &g_xz[dir][b][0][0];
    float acc = cb[d];
    #pragma unroll
    for (int i = 0; i < 4; i++) {
        int tt = t - 3 + i;
        if (tt >= 0) acc += cw[d*4 + i] * xi[(long)tt * (2*DI) + d];
    }
    g_xc[dir][b][t][d] = acc / (1.f + __expf(-acc));
}

// ----------------------------- delta (softplus of dt proj), du, B/C repack -----------------------------
__global__ __launch_bounds__(256) void dt_bc_kernel(
    const float* __restrict__ dtw0, const float* __restrict__ dtb0,
    const float* __restrict__ dtw1, const float* __restrict__ dtb1)
{
    const int bid = blockIdx.x;            // 0..127
    const int chunk = bid & 31;
    const int b = (bid >> 5) & 1;
    const int dir = bid >> 6;
    const int t0 = chunk * 128;
    __shared__ float sx[128 * XW];
    const float* src = &g_xdbl[dir][b][t0][0];
    for (int i = threadIdx.x; i < 128 * XW; i += 256) sx[i] = src[i];
    __syncthreads();
    const float* dtw = dir ? dtw1 : dtw0;
    const float* dtb = dir ? dtb1 : dtb0;
    for (int idx = threadIdx.x; idx < 128 * DI; idx += 256) {
        int tl = idx / DI, d = idx % DI;
        float s = dtb[d];
        const float* xr = &sx[tl * XW];
        #pragma unroll
        for (int r = 0; r < DR; r++) s += xr[r] * __ldg(&dtw[d*DR + r]);
        float dlt = (s > 20.f) ? s : log1pf(__expf(s));
        int t = t0 + tl;
        float xc = g_xc[dir][b][t][d];
        g_delta[dir][b][t][d] = dlt;
        g_du[dir][b][t][d] = dlt * xc;
    }
    for (int idx = threadIdx.x; idx < 2 * DS * 128; idx += 256) {
        int tl = idx & 127;
        int n  = (idx >> 7) & 15;
        int which = idx >> 11;              // 0 = B, 1 = C
        int t = t0 + tl;
        float v = sx[tl * XW + DR + which * DS + n];
        float* dst = which ? &g_Cc[dir][b][0][0][0] : &g_Bc[dir][b][0][0][0];
        dst[(t >> 2) * (DS*4) + n * 4 + (t & 3)] = v;
    }
}

// ----------------------------- selective scan: thread = (dir,b,d,n) -----------------------------
__global__ __launch_bounds__(256) void scan_kernel(
    const float* __restrict__ Al0, const float* __restrict__ Al1)
{
    const int gid = blockIdx.x * 256 + threadIdx.x;
    const int n  = gid & 15;
    const int cj = gid >> 4;               // 0..3071
    const int dir = cj / (NB * DI);
    const int rem = cj % (NB * DI);
    const int b = rem / DI;
    const int d = rem % DI;
    const float* Al = dir ? Al1 : Al0;
    const float Acoef = -__expf(Al[d*DS + n]);
    const float*  pd = &g_delta[dir][b][0][0];
    const float*  pu = &g_du[dir][b][0][0];
    const float4* pB = (const float4*)&g_Bc[dir][b][0][0][0];
    const float4* pC = (const float4*)&g_Cc[dir][b][0][0][0];
    float* py = &g_y[dir][b][0][0];
    float h = 0.f;
    for (int t4 = 0; t4 < LL/4; t4++) {
        float4 Bv = __ldg(&pB[t4*16 + n]);
        float4 Cv = __ldg(&pC[t4*16 + n]);
        #pragma unroll
        for (int j = 0; j < 4; j++) {
            int t = t4*4 + j;
            float dlt = __ldg(&pd[(long)t*DI + d]);
            float du  = __ldg(&pu[(long)t*DI + d]);
            float Bj = (j==0) ? Bv.x : (j==1) ? Bv.y : (j==2) ? Bv.z : Bv.w;
            float Cj = (j==0) ? Cv.x : (j==1) ? Cv.y : (j==2) ? Cv.z : Cv.w;
            float dA = __expf(dlt * Acoef);
            h = fmaf(dA, h, du * Bj);
            float p = h * Cj;
            p += __shfl_xor_sync(0xffffffffu, p, 1);
            p += __shfl_xor_sync(0xffffffffu, p, 2);
            p += __shfl_xor_sync(0xffffffffu, p, 4);
            p += __shfl_xor_sync(0xffffffffu, p, 8);
            if (n == 0) py[(long)t*DI + d] = p;
        }
    }
}

// ----------------------------- gate: (y + xc*D) * silu(z), into g_delta (reuse) -----------------------------
__global__ __launch_bounds__(256) void gate_kernel(
    const float* __restrict__ D0, const float* __restrict__ D1)
{
    long id = (long)blockIdx.x * 256 + threadIdx.x;
    const long total = (long)2 * NB * LL * DI;
    if (id >= total) return;
    int d = (int)(id % DI); long r = id / DI;
    int t = (int)(r % LL); r /= LL;
    int b = (int)(r % NB); int dir = (int)(r / NB);
    float Dp = (dir ? D1 : D0)[d];
    float y = g_y[dir][b][t][d] + g_xc[dir][b][t][d] * Dp;
    float z = g_xz[dir][b][t][DI + d];
    float sz = z / (1.f + __expf(-z));
    g_delta[dir][b][t][d] = y * sz;
}

// ----------------------------- GLU + partial stats -----------------------------
__global__ __launch_bounds__(256) void glu_kernel()
{
    const int batch = blockIdx.y;
    const int tid = threadIdx.x;
    float lsum = 0.f, lssq = 0.f;
    const float* yc = &g_yc[batch][0][0];
    float* gl = &g_glu[batch][0][0];
    for (int it = 0; it < 128; it++) {
        long e = (long)blockIdx.x * 32768 + (long)it * 256 + tid;
        int t = (int)(e / DM), o = (int)(e % DM);
        float a  = yc[(long)t * (2*DM) + o];
        float bg = yc[(long)t * (2*DM) + DM + o];
        float g = a * (1.f / (1.f + __expf(-bg)));
        gl[e] = g;
        lsum += g; lssq += g * g;
    }
    __shared__ float s1[256], s2[256];
    s1[tid] = lsum; s2[tid] = lssq;
    __syncthreads();
    for (int s = 128; s > 0; s >>= 1) {
        if (tid < s) { s1[tid] += s1[tid+s]; s2[tid] += s2[tid+s]; }
        __syncthreads();
    }
    if (tid == 0) g_part[batch][blockIdx.x] = make_float2(s1[0], s2[0]);
}

__global__ void stats_kernel()
{
    int b = threadIdx.x;
    if (b < NB) {
        float sum = 0.f, ssq = 0.f;
        for (int i = 0; i < 48; i++) { float2 p = g_part[b][i]; sum += p.x; ssq += p.y; }
        const float inv = 1.f / ((float)DM * (float)LL);
        float mu = sum * inv;
        float var = ssq * inv - mu * mu;
        g_stats[b] = make_float2(mu, rsqrtf(var + 1e-5f));
    }
}

// ----------------------------- normalize + transpose to output [b][c][t] -----------------------------
__global__ __launch_bounds__(256) void norm_kernel(
    const float* __restrict__ gnw, const float* __restrict__ gnb,
    float* __restrict__ out)
{
    __shared__ float s[32][33];
    const int b = blockIdx.z;
    const int t0 = blockIdx.x * 32;
    const int c0 = blockIdx.y * 32;
    const int tx = threadIdx.x & 31;
    const int ty = threadIdx.x >> 5;        // 0..7
    #pragma unroll
    for (int j = 0; j < 4; j++) {
        int t = t0 + ty + j*8;
        s[ty + j*8][tx] = g_glu[b][t][c0 + tx];
    }
    __syncthreads();
    float2 st = g_stats[b];
    #pragma unroll
    for (int j = 0; j < 4; j++) {
        int c = c0 + ty + j*8;
        float v = s[tx][ty + j*8];
        out[((long)b * DM + c) * LL + t0 + tx] = (v - st.x) * st.y * gnw[c] + gnb[c];
    }
}

// ----------------------------- launch -----------------------------
extern "C" void kernel_launch(void* const* d_in, const int* in_sizes, int n_in,
                              void* d_out, int out_size)
{
    (void)in_sizes; (void)n_in; (void)out_size;
    const float* x        = (const float*)d_in[0];
    const float* f_in_w   = (const float*)d_in[1];
    const float* f_conv_w = (const float*)d_in[2];
    const float* f_conv_b = (const float*)d_in[3];
    const float* f_xproj  = (const float*)d_in[4];
    const float* f_dt_w   = (const float*)d_in[5];
    const float* f_dt_b   = (const float*)d_in[6];
    const float* f_A_log  = (const float*)d_in[7];
    const float* f_D      = (const float*)d_in[8];
    const float* f_out_w  = (const float*)d_in[9];
    const float* b_in_w   = (const float*)d_in[10];
    const float* b_conv_w = (const float*)d_in[11];
    const float* b_conv_b = (const float*)d_in[12];
    const float* b_xproj  = (const float*)d_in[13];
    const float* b_dt_w   = (const float*)d_in[14];
    const float* b_dt_b   = (const float*)d_in[15];
    const float* b_A_log  = (const float*)d_in[16];
    const float* b_D      = (const float*)d_in[17];
    const float* b_out_w  = (const float*)d_in[18];
    const float* c_w      = (const float*)d_in[19];
    const float* c_b      = (const float*)d_in[20];
    const float* gn_w     = (const float*)d_in[21];
    const float* gn_b     = (const float*)d_in[22];
    float* out = (float*)d_out;

    float *pxz, *pxc, *pxdbl, *pgate, *pycat, *pyc;
    cudaGetSymbolAddress((void**)&pxz,   g_xz);
    cudaGetSymbolAddress((void**)&pxc,   g_xc);
    cudaGetSymbolAddress((void**)&pxdbl, g_xdbl);
    cudaGetSymbolAddress((void**)&pgate, g_delta);   // reused as gate output
    cudaGetSymbolAddress((void**)&pycat, g_ycat);
    cudaGetSymbolAddress((void**)&pyc,   g_yc);

    // 1) in-projection, both dirs + batches
    gemm_inproj<<<dim3(2*DI/64, LL/64, 4), 256>>>(x, f_in_w, b_in_w);

    // 2) depthwise causal conv + silu
    {
        long total = (long)2 * NB * LL * DI;
        conv_silu_kernel<<<(unsigned)((total + 255) / 256), 256>>>(f_conv_w, f_conv_b, b_conv_w, b_conv_b);
    }

    // 3) x-projection -> xdbl (N=56)
    gemm_generic<<<dim3(1, (NB*LL)/64, 2), 256>>>(
        pxc, DI, (long)NB*LL*DI,
        f_xproj, b_xproj, nullptr,
        pxdbl, XW, (long)NB*LL*XW,
        XW, DI);

    // 4) delta = softplus(dt proj), du = delta*xc, repack B/C
    dt_bc_kernel<<<128, 256>>>(f_dt_w, f_dt_b, b_dt_w, b_dt_b);

    // 5) selective scan
    scan_kernel<<<192, 256>>>(f_A_log, b_A_log);

    // 6) gate
    {
        long total = (long)2 * NB * LL * DI;
        gate_kernel<<<(unsigned)((total + 255) / 256), 256>>>(f_D, b_D);
    }

    // 7) out-projection -> concat buffer (dir selects column half)
    gemm_generic<<<dim3(DM/64, (NB*LL)/64, 2), 256>>>(
        pgate, DI, (long)NB*LL*DI,
        f_out_w, b_out_w, nullptr,
        pycat, 2*DM, (long)DM,
        DM, DI);

    // 8) final 1x1 conv (c_w) + bias
    gemm_generic<<<dim3(2*DM/64, (NB*LL)/64, 1), 256>>>(
        pycat, 2*DM, 0L,
        c_w, c_w, c_b,
        pyc, 2*DM, 0L,
        2*DM, 2*DM);

    // 9) GLU + partial stats; 10) stats; 11) normalize + transpose out
    glu_kernel<<<dim3(48, 2), 256>>>();
    stats_kernel<<<1, 32>>>();
    norm_kernel<<<dim3(LL/32, DM/32, NB), 256>>>(gn_w, gn_b, out);
}

// round 4
// speedup vs baseline: 1.1320x; 1.1320x over previous
#include <cuda_runtime.h>

#define LL 4096
#define DM 384
#define DI 768
#define DS 16
#define DR 24
#define NB 2
#define XW (DR + 2*DS)   // 56

// ----------------------------- scratch (device globals) -----------------------------
__device__ float g_xz   [2][NB][LL][2*DI];   // in-proj output: [0..767]=xi, [768..1535]=z
__device__ float g_xc   [2][NB][LL][DI];     // after causal conv + silu
__device__ float g_xdbl [2][NB][LL][XW];     // x-proj output (dt | B | C)
__device__ float g_delta[2][NB][LL][DI];     // softplus(dt@dtw+b); later reused as gate output
__device__ float g_du   [2][NB][LL][DI];     // delta * xc
__device__ float g_Bc   [2][NB][LL/4][DS][4];// B repacked [t/4][n][t%4]
__device__ float g_Cc   [2][NB][LL/4][DS][4];
__device__ float g_y    [2][NB][LL][DI];     // scan output
__device__ float g_ycat [NB][LL][2*DM];      // concat(yf, yb) rows (b,t)
__device__ float g_yc   [NB][LL][2*DM];      // after final 1x1 conv + bias
__device__ float g_glu  [NB][LL][DM];        // a * sigmoid(b)
__device__ float2 g_part[NB][64];
__device__ float2 g_stats[NB];

// ----------------------------- f32x2 helpers -----------------------------
__device__ __forceinline__ unsigned long long dup2(float x){
    unsigned long long r; asm("mov.b64 %0, {%1, %1};" : "=l"(r) : "f"(x)); return r;
}
__device__ __forceinline__ void ffma2(unsigned long long &d, unsigned long long a, unsigned long long b){
    asm("fma.rn.f32x2 %0, %1, %2, %0;" : "+l"(d) : "l"(a), "l"(b));
}
__device__ __forceinline__ float2 unpk2(unsigned long long v){
    float2 f; asm("mov.b64 {%0, %1}, %2;" : "=f"(f.x), "=f"(f.y) : "l"(v)); return f;
}

// ===========================================================================
// GEMM 128x64 tile, 8x4 microtile, f32x2. A row-major [M][lda], W [N][K].
// ===========================================================================
__global__ __launch_bounds__(256) void gemm128(
    const float* __restrict__ A, int lda, long Az,
    const float* __restrict__ W0, const float* __restrict__ W1,
    const float* __restrict__ bias,
    float* __restrict__ C, int ldc, long Cz,
    int N, int K)
{
    __shared__ float As[16][128];
    __shared__ float Bs[16][64];
    const int z = blockIdx.z;
    const float* Ab = A + (long)z * Az;
    const float* W  = (z == 0) ? W0 : W1;
    float* Cb = C + (long)z * Cz;
    const int row0 = blockIdx.y * 128;
    const int col0 = blockIdx.x * 64;
    const int tid = threadIdx.x;
    const int tx = tid & 15, ty = tid >> 4;      // microtile coords

    const int am = tid & 127;                    // A loader: m in tile
    const int akq = tid >> 7;                    // 0..1 -> k-halves of 8
    const int wn = tid & 63;                     // B loader: n in tile
    const int wkq = tid >> 6;                    // 0..3 -> k-quarters of 4
    const bool wok = (col0 + wn) < N;

    unsigned long long acc[4][4];
    #pragma unroll
    for (int i = 0; i < 4; i++)
        #pragma unroll
        for (int j = 0; j < 4; j++) acc[i][j] = 0ull;

    for (int k0 = 0; k0 < K; k0 += 16) {
        {
            const float* ar = &Ab[(long)(row0 + am) * lda + k0 + akq * 8];
            float4 v0 = *(const float4*)ar;
            float4 v1 = *(const float4*)(ar + 4);
            As[akq*8+0][am] = v0.x; As[akq*8+1][am] = v0.y;
            As[akq*8+2][am] = v0.z; As[akq*8+3][am] = v0.w;
            As[akq*8+4][am] = v1.x; As[akq*8+5][am] = v1.y;
            As[akq*8+6][am] = v1.z; As[akq*8+7][am] = v1.w;
        }
        {
            float4 v = make_float4(0.f, 0.f, 0.f, 0.f);
            if (wok) v = *(const float4*)&W[(long)(col0 + wn) * K + k0 + wkq * 4];
            Bs[wkq*4+0][wn] = v.x; Bs[wkq*4+1][wn] = v.y;
            Bs[wkq*4+2][wn] = v.z; Bs[wkq*4+3][wn] = v.w;
        }
        __syncthreads();
        #pragma unroll
        for (int k = 0; k < 16; k++) {
            unsigned long long a01 = *(const unsigned long long*)&As[k][ty*8];
            unsigned long long a23 = *(const unsigned long long*)&As[k][ty*8+2];
            unsigned long long a45 = *(const unsigned long long*)&As[k][ty*8+4];
            unsigned long long a67 = *(const unsigned long long*)&As[k][ty*8+6];
            float4 bv = *(const float4*)&Bs[k][tx*4];
            unsigned long long b0 = dup2(bv.x), b1 = dup2(bv.y), b2 = dup2(bv.z), b3 = dup2(bv.w);
            ffma2(acc[0][0], a01, b0); ffma2(acc[0][1], a01, b1);
            ffma2(acc[0][2], a01, b2); ffma2(acc[0][3], a01, b3);
            ffma2(acc[1][0], a23, b0); ffma2(acc[1][1], a23, b1);
            ffma2(acc[1][2], a23, b2); ffma2(acc[1][3], a23, b3);
            ffma2(acc[2][0], a45, b0); ffma2(acc[2][1], a45, b1);
            ffma2(acc[2][2], a45, b2); ffma2(acc[2][3], a45, b3);
            ffma2(acc[3][0], a67, b0); ffma2(acc[3][1], a67, b1);
            ffma2(acc[3][2], a67, b2); ffma2(acc[3][3], a67, b3);
        }
        __syncthreads();
    }
    const int colb = col0 + tx*4;
    float bsv[4] = {0.f, 0.f, 0.f, 0.f};
    if (bias) {
        #pragma unroll
        for (int j = 0; j < 4; j++) if (colb + j < N) bsv[j] = bias[colb + j];
    }
    #pragma unroll
    for (int p = 0; p < 4; p++) {
        float2 f0 = unpk2(acc[p][0]), f1 = unpk2(acc[p][1]);
        float2 f2 = unpk2(acc[p][2]), f3 = unpk2(acc[p][3]);
        long r0 = (long)(row0 + ty*8 + 2*p) * ldc;
        long r1 = r0 + ldc;
        if (colb + 3 < N) {
            *(float4*)&Cb[r0 + colb] = make_float4(f0.x+bsv[0], f1.x+bsv[1], f2.x+bsv[2], f3.x+bsv[3]);
            *(float4*)&Cb[r1 + colb] = make_float4(f0.y+bsv[0], f1.y+bsv[1], f2.y+bsv[2], f3.y+bsv[3]);
        } else {
            float o0[4] = {f0.x, f1.x, f2.x, f3.x};
            float o1[4] = {f0.y, f1.y, f2.y, f3.y};
            #pragma unroll
            for (int j = 0; j < 4; j++) if (colb + j < N) {
                Cb[r0 + colb + j] = o0[j] + bsv[j];
                Cb[r1 + colb + j] = o1[j] + bsv[j];
            }
        }
    }
}

// ===========================================================================
// in-proj GEMM: A = x[b][k][ts(t)] gather (fwd/bwd time-reversal), 128x64 tile
// ===========================================================================
__global__ __launch_bounds__(256) void gemm_inproj128(
    const float* __restrict__ x,
    const float* __restrict__ W0, const float* __restrict__ W1)
{
    __shared__ float As[16][128];
    __shared__ float Bs[16][64];
    const int z = blockIdx.z;            // dir*2 + b
    const int dir = z >> 1, b = z & 1;
    const float* W  = dir ? W1 : W0;
    const float* xb = x + (long)b * DM * LL;
    float* Cb = &g_xz[dir][b][0][0];
    const int row0 = blockIdx.y * 128;   // t tile
    const int col0 = blockIdx.x * 64;    // n tile
    const int tid = threadIdx.x;
    const int tx = tid & 15, ty = tid >> 4;

    const int am = tid & 127;
    const int akq = tid >> 7;            // 0..1
    const int wn = tid & 63;
    const int wkq = tid >> 6;            // 0..3

    unsigned long long acc[4][4];
    #pragma unroll
    for (int i = 0; i < 4; i++)
        #pragma unroll
        for (int j = 0; j < 4; j++) acc[i][j] = 0ull;

    const int t = row0 + am;
    const int ts = dir ? (LL - 1 - t) : t;

    for (int k0 = 0; k0 < DM; k0 += 16) {
        #pragma unroll
        for (int i = 0; i < 8; i++) {
            int k = akq * 8 + i;
            As[k][am] = xb[(long)(k0 + k) * LL + ts];
        }
        {
            float4 v = *(const float4*)&W[(long)(col0 + wn) * DM + k0 + wkq * 4];
            Bs[wkq*4+0][wn] = v.x; Bs[wkq*4+1][wn] = v.y;
            Bs[wkq*4+2][wn] = v.z; Bs[wkq*4+3][wn] = v.w;
        }
        __syncthreads();
        #pragma unroll
        for (int k = 0; k < 16; k++) {
            unsigned long long a01 = *(const unsigned long long*)&As[k][ty*8];
            unsigned long long a23 = *(const unsigned long long*)&As[k][ty*8+2];
            unsigned long long a45 = *(const unsigned long long*)&As[k][ty*8+4];
            unsigned long long a67 = *(const unsigned long long*)&As[k][ty*8+6];
            float4 bv = *(const float4*)&Bs[k][tx*4];
            unsigned long long b0 = dup2(bv.x), b1 = dup2(bv.y), b2 = dup2(bv.z), b3 = dup2(bv.w);
            ffma2(acc[0][0], a01, b0); ffma2(acc[0][1], a01, b1);
            ffma2(acc[0][2], a01, b2); ffma2(acc[0][3], a01, b3);
            ffma2(acc[1][0], a23, b0); ffma2(acc[1][1], a23, b1);
            ffma2(acc[1][2], a23, b2); ffma2(acc[1][3], a23, b3);
            ffma2(acc[2][0], a45, b0); ffma2(acc[2][1], a45, b1);
            ffma2(acc[2][2], a45, b2); ffma2(acc[2][3], a45, b3);
            ffma2(acc[3][0], a67, b0); ffma2(acc[3][1], a67, b1);
            ffma2(acc[3][2], a67, b2); ffma2(acc[3][3], a67, b3);
        }
        __syncthreads();
    }
    const int colb = col0 + tx*4;
    #pragma unroll
    for (int p = 0; p < 4; p++) {
        float2 f0 = unpk2(acc[p][0]), f1 = unpk2(acc[p][1]);
        float2 f2 = unpk2(acc[p][2]), f3 = unpk2(acc[p][3]);
        long r0 = (long)(row0 + ty*8 + 2*p) * (2*DI);
        long r1 = r0 + 2*DI;
        *(float4*)&Cb[r0 + colb] = make_float4(f0.x, f1.x, f2.x, f3.x);
        *(float4*)&Cb[r1 + colb] = make_float4(f0.y, f1.y, f2.y, f3.y);
    }
}

// ===========================================================================
// delta GEMM: delta = softplus(dt @ dtw^T + dtb); du = delta * xc
// M = NB*LL (rows of g_xdbl per dir), N = DI, K = DR(=24). Tile 64x64.
// ===========================================================================
__global__ __launch_bounds__(256) void delta_gemm(
    const float* __restrict__ dtw0, const float* __restrict__ dtb0,
    const float* __restrict__ dtw1, const float* __restrict__ dtb1)
{
    __shared__ float As[DR][64];
    __shared__ float Bs[DR][64];
    const int dir = blockIdx.z;
    const float* Ab  = &g_xdbl[dir][0][0][0];
    const float* xcb = &g_xc[dir][0][0][0];
    float* pdl = &g_delta[dir][0][0][0];
    float* pdu = &g_du[dir][0][0][0];
    const float* dtw = dir ? dtw1 : dtw0;
    const float* dtb = dir ? dtb1 : dtb0;
    const int row0 = blockIdx.y * 64;
    const int col0 = blockIdx.x * 64;
    const int tid = threadIdx.x;
    const int tx = tid & 15, ty = tid >> 4;

    for (int i = tid; i < 64 * DR; i += 256) {
        int r = i / DR, k = i % DR;
        As[k][r] = Ab[(long)(row0 + r) * XW + k];
        Bs[k][r] = dtw[(long)(col0 + r) * DR + k];
    }
    __syncthreads();

    unsigned long long acc[2][4];
    #pragma unroll
    for (int i = 0; i < 2; i++)
        #pragma unroll
        for (int j = 0; j < 4; j++) acc[i][j] = 0ull;

    #pragma unroll
    for (int k = 0; k < DR; k++) {
        unsigned long long a01 = *(const unsigned long long*)&As[k][ty*4];
        unsigned long long a23 = *(const unsigned long long*)&As[k][ty*4+2];
        float4 bv = *(const float4*)&Bs[k][tx*4];
        unsigned long long b0 = dup2(bv.x), b1 = dup2(bv.y), b2 = dup2(bv.z), b3 = dup2(bv.w);
        ffma2(acc[0][0], a01, b0); ffma2(acc[0][1], a01, b1);
        ffma2(acc[0][2], a01, b2); ffma2(acc[0][3], a01, b3);
        ffma2(acc[1][0], a23, b0); ffma2(acc[1][1], a23, b1);
        ffma2(acc[1][2], a23, b2); ffma2(acc[1][3], a23, b3);
    }
    const int colb = col0 + tx*4;
    float4 bias4 = *(const float4*)&dtb[colb];
    float bsv[4] = {bias4.x, bias4.y, bias4.z, bias4.w};
    float out[4][4];
    #pragma unroll
    for (int i = 0; i < 2; i++)
        #pragma unroll
        for (int j = 0; j < 4; j++) {
            float2 f = unpk2(acc[i][j]);
            out[2*i][j] = f.x; out[2*i+1][j] = f.y;
        }
    #pragma unroll
    for (int r = 0; r < 4; r++) {
        long row = row0 + ty*4 + r;
        float4 xc4 = *(const float4*)&xcb[row * DI + colb];
        float xcv[4] = {xc4.x, xc4.y, xc4.z, xc4.w};
        float dl[4], du[4];
        #pragma unroll
        for (int j = 0; j < 4; j++) {
            float s = out[r][j] + bsv[j];
            float sp = fmaxf(s, 0.f) + log1pf(__expf(-fabsf(s)));
            dl[j] = sp;
            du[j] = sp * xcv[j];
        }
        *(float4*)&pdl[row * DI + colb] = make_float4(dl[0], dl[1], dl[2], dl[3]);
        *(float4*)&pdu[row * DI + colb] = make_float4(du[0], du[1], du[2], du[3]);
    }
}

// ----------------------------- B/C repack -----------------------------
// total elements: 2 dirs * NB * LL * 2 tensors * DS = 524288
__global__ __launch_bounds__(256) void repack_kernel()
{
    int id = blockIdx.x * 256 + threadIdx.x;
    if (id >= 2 * NB * LL * 2 * DS) return;
    int n = id & 15;
    int which = (id >> 4) & 1;
    int t = (id >> 5) & (LL - 1);
    int b = (id >> 17) & 1;
    int dir = (id >> 18) & 1;
    float v = g_xdbl[dir][b][t][DR + which * DS + n];
    float* dst = which ? &g_Cc[dir][b][0][0][0] : &g_Bc[dir][b][0][0][0];
    dst[(t >> 2) * (DS*4) + n * 4 + (t & 3)] = v;
}

// ----------------------------- depthwise causal conv + silu -----------------------------
__global__ __launch_bounds__(256) void conv_silu_kernel(
    const float* __restrict__ cw0, const float* __restrict__ cb0,
    const float* __restrict__ cw1, const float* __restrict__ cb1)
{
    long id = (long)blockIdx.x * 256 + threadIdx.x;
    const long total = (long)2 * NB * LL * DI;
    if (id >= total) return;
    int d = (int)(id % DI); long r = id / DI;
    int t = (int)(r % LL); r /= LL;
    int b = (int)(r % NB); int dir = (int)(r / NB);
    const float* cw = dir ? cw1 : cw0;
    const float* cb = dir ? cb1 : cb0;
    const float* xi = &g_xz[dir][b][0][0];
    float acc = cb[d];
    #pragma unroll
    for (int i = 0; i < 4; i++) {
        int tt = t - 3 + i;
        if (tt >= 0) acc += cw[d*4 + i] * xi[(long)tt * (2*DI) + d];
    }
    g_xc[dir][b][t][d] = acc / (1.f + __expf(-acc));
}

// ----------------------------- selective scan: thread = (dir,b,d,n) -----------------------------
__global__ __launch_bounds__(256) void scan_kernel(
    const float* __restrict__ Al0, const float* __restrict__ Al1)
{
    const int gid = blockIdx.x * 256 + threadIdx.x;
    const int n  = gid & 15;
    const int cj = gid >> 4;               // 0..3071
    const int dir = cj / (NB * DI);
    const int rem = cj % (NB * DI);
    const int b = rem / DI;
    const int d = rem % DI;
    const float* Al = dir ? Al1 : Al0;
    const float Acoef = -__expf(Al[d*DS + n]);
    const float*  pd = &g_delta[dir][b][0][0];
    const float*  pu = &g_du[dir][b][0][0];
    const float4* pB = (const float4*)&g_Bc[dir][b][0][0][0];
    const float4* pC = (const float4*)&g_Cc[dir][b][0][0][0];
    float* py = &g_y[dir][b][0][0];
    float h = 0.f;
    float4 Bv = __ldg(&pB[n]);
    float4 Cv = __ldg(&pC[n]);
    for (int t4 = 0; t4 < LL/4; t4++) {
        float4 Bn = make_float4(0.f,0.f,0.f,0.f), Cn = Bn;
        if (t4 + 1 < LL/4) {
            Bn = __ldg(&pB[(t4+1)*16 + n]);
            Cn = __ldg(&pC[(t4+1)*16 + n]);
        }
        float dl[4], uu[4];
        #pragma unroll
        for (int j = 0; j < 4; j++) {
            long o = (long)(t4*4 + j) * DI + d;
            dl[j] = __ldg(pd + o);
            uu[j] = __ldg(pu + o);
        }
        float dA[4];
        #pragma unroll
        for (int j = 0; j < 4; j++) dA[j] = __expf(dl[j] * Acoef);
        #pragma unroll
        for (int j = 0; j < 4; j++) {
            int t = t4*4 + j;
            float Bj = (j==0) ? Bv.x : (j==1) ? Bv.y : (j==2) ? Bv.z : Bv.w;
            float Cj = (j==0) ? Cv.x : (j==1) ? Cv.y : (j==2) ? Cv.z : Cv.w;
            h = fmaf(dA[j], h, uu[j] * Bj);
            float p = h * Cj;
            p += __shfl_xor_sync(0xffffffffu, p, 1);
            p += __shfl_xor_sync(0xffffffffu, p, 2);
            p += __shfl_xor_sync(0xffffffffu, p, 4);
            p += __shfl_xor_sync(0xffffffffu, p, 8);
            if (n == 0) py[(long)t*DI + d] = p;
        }
        Bv = Bn; Cv = Cn;
    }
}

// ----------------------------- gate: (y + xc*D) * silu(z), into g_delta (reuse) -----------------------------
__global__ __launch_bounds__(256) void gate_kernel(
    const float* __restrict__ D0, const float* __restrict__ D1)
{
    long id = (long)blockIdx.x * 256 + threadIdx.x;
    const long total = (long)2 * NB * LL * DI;
    if (id >= total) return;
    int d = (int)(id % DI); long r = id / DI;
    int t = (int)(r % LL); r /= LL;
    int b = (int)(r % NB); int dir = (int)(r / NB);
    float Dp = (dir ? D1 : D0)[d];
    float y = g_y[dir][b][t][d] + g_xc[dir][b][t][d] * Dp;
    float z = g_xz[dir][b][t][DI + d];
    float sz = z / (1.f + __expf(-z));
    g_delta[dir][b][t][d] = y * sz;
}

// ----------------------------- GLU + partial stats -----------------------------
__global__ __launch_bounds__(256) void glu_kernel()
{
    const int batch = blockIdx.y;
    const int tid = threadIdx.x;
    float lsum = 0.f, lssq = 0.f;
    const float* yc = &g_yc[batch][0][0];
    float* gl = &g_glu[batch][0][0];
    for (int it = 0; it < 128; it++) {
        long e = (long)blockIdx.x * 32768 + (long)it * 256 + tid;
        int t = (int)(e / DM), o = (int)(e % DM);
        float a  = yc[(long)t * (2*DM) + o];
        float bg = yc[(long)t * (2*DM) + DM + o];
        float g = a * (1.f / (1.f + __expf(-bg)));
        gl[e] = g;
        lsum += g; lssq += g * g;
    }
    __shared__ float s1[256], s2[256];
    s1[tid] = lsum; s2[tid] = lssq;
    __syncthreads();
    for (int s = 128; s > 0; s >>= 1) {
        if (tid < s) { s1[tid] += s1[tid+s]; s2[tid] += s2[tid+s]; }
        __syncthreads();
    }
    if (tid == 0) g_part[batch][blockIdx.x] = make_float2(s1[0], s2[0]);
}

__global__ void stats_kernel()
{
    int b = threadIdx.x;
    if (b < NB) {
        float sum = 0.f, ssq = 0.f;
        for (int i = 0; i < 48; i++) { float2 p = g_part[b][i]; sum += p.x; ssq += p.y; }
        const float inv = 1.f / ((float)DM * (float)LL);
        float mu = sum * inv;
        float var = ssq * inv - mu * mu;
        g_stats[b] = make_float2(mu, rsqrtf(var + 1e-5f));
    }
}

// ----------------------------- normalize + transpose to output [b][c][t] -----------------------------
__global__ __launch_bounds__(256) void norm_kernel(
    const float* __restrict__ gnw, const float* __restrict__ gnb,
    float* __restrict__ out)
{
    __shared__ float s[32][33];
    const int b = blockIdx.z;
    const int t0 = blockIdx.x * 32;
    const int c0 = blockIdx.y * 32;
    const int tx = threadIdx.x & 31;
    const int ty = threadIdx.x >> 5;        // 0..7
    #pragma unroll
    for (int j = 0; j < 4; j++) {
        int t = t0 + ty + j*8;
        s[ty + j*8][tx] = g_glu[b][t][c0 + tx];
    }
    __syncthreads();
    float2 st = g_stats[b];
    #pragma unroll
    for (int j = 0; j < 4; j++) {
        int c = c0 + ty + j*8;
        float v = s[tx][ty + j*8];
        out[((long)b * DM + c) * LL + t0 + tx] = (v - st.x) * st.y * gnw[c] + gnb[c];
    }
}

// ----------------------------- launch -----------------------------
extern "C" void kernel_launch(void* const* d_in, const int* in_sizes, int n_in,
                              void* d_out, int out_size)
{
    (void)in_sizes; (void)n_in; (void)out_size;
    const float* x        = (const float*)d_in[0];
    const float* f_in_w   = (const float*)d_in[1];
    const float* f_conv_w = (const float*)d_in[2];
    const float* f_conv_b = (const float*)d_in[3];
    const float* f_xproj  = (const float*)d_in[4];
    const float* f_dt_w   = (const float*)d_in[5];
    const float* f_dt_b   = (const float*)d_in[6];
    const float* f_A_log  = (const float*)d_in[7];
    const float* f_D      = (const float*)d_in[8];
    const float* f_out_w  = (const float*)d_in[9];
    const float* b_in_w   = (const float*)d_in[10];
    const float* b_conv_w = (const float*)d_in[11];
    const float* b_conv_b = (const float*)d_in[12];
    const float* b_xproj  = (const float*)d_in[13];
    const float* b_dt_w   = (const float*)d_in[14];
    const float* b_dt_b   = (const float*)d_in[15];
    const float* b_A_log  = (const float*)d_in[16];
    const float* b_D      = (const float*)d_in[17];
    const float* b_out_w  = (const float*)d_in[18];
    const float* c_w      = (const float*)d_in[19];
    const float* c_b      = (const float*)d_in[20];
    const float* gn_w     = (const float*)d_in[21];
    const float* gn_b     = (const float*)d_in[22];
    float* out = (float*)d_out;

    float *pxc, *pxdbl, *pgate, *pycat, *pyc;
    cudaGetSymbolAddress((void**)&pxc,   g_xc);
    cudaGetSymbolAddress((void**)&pxdbl, g_xdbl);
    cudaGetSymbolAddress((void**)&pgate, g_delta);   // reused as gate output
    cudaGetSymbolAddress((void**)&pycat, g_ycat);
    cudaGetSymbolAddress((void**)&pyc,   g_yc);

    // 1) in-projection, both dirs + batches
    gemm_inproj128<<<dim3(2*DI/64, LL/128, 4), 256>>>(x, f_in_w, b_in_w);

    // 2) depthwise causal conv + silu
    {
        long total = (long)2 * NB * LL * DI;
        conv_silu_kernel<<<(unsigned)((total + 255) / 256), 256>>>(f_conv_w, f_conv_b, b_conv_w, b_conv_b);
    }

    // 3) x-projection -> xdbl (N=56)
    gemm128<<<dim3(1, (NB*LL)/128, 2), 256>>>(
        pxc, DI, (long)NB*LL*DI,
        f_xproj, b_xproj, nullptr,
        pxdbl, XW, (long)NB*LL*XW,
        XW, DI);

    // 4) delta = softplus(dt @ dtw^T + dtb), du = delta*xc  (GEMM, fused epilogue)
    delta_gemm<<<dim3(DI/64, (NB*LL)/64, 2), 256>>>(f_dt_w, f_dt_b, b_dt_w, b_dt_b);

    // 4b) repack B/C for scan  (524288 elems -> 2048 blocks of 256)
    repack_kernel<<<2048, 256>>>();

    // 5) selective scan
    scan_kernel<<<192, 256>>>(f_A_log, b_A_log);

    // 6) gate
    {
        long total = (long)2 * NB * LL * DI;
        gate_kernel<<<(unsigned)((total + 255) / 256), 256>>>(f_D, b_D);
    }

    // 7) out-projection -> concat buffer (dir selects column half)
    gemm128<<<dim3(DM/64, (NB*LL)/128, 2), 256>>>(
        pgate, DI, (long)NB*LL*DI,
        f_out_w, b_out_w, nullptr,
        pycat, 2*DM, (long)DM,
        DM, DI);

    // 8) final 1x1 conv (c_w) + bias
    gemm128<<<dim3(2*DM/64, (NB*LL)/128, 1), 256>>>(
        pycat, 2*DM, 0L,
        c_w, c_w, c_b,
        pyc, 2*DM, 0L,
        2*DM, 2*DM);

    // 9) GLU + partial stats; 10) stats; 11) normalize + transpose out
    glu_kernel<<<dim3(48, 2), 256>>>();
    stats_kernel<<<1, 32>>>();
    norm_kernel<<<dim3(LL/32, DM/32, NB), 256>>>(gn_w, gn_b, out);
}

// round 7
// speedup vs baseline: 1.5094x; 1.3334x over previous
#include <cuda_runtime.h>
#include <cuda_bf16.h>
#include <cstdint>

#define LL 4096
#define DM 384
#define DI 768
#define DS 16
#define DR 24
#define NB 2
#define XW (DR + 2*DS)   // 56

// ----------------------------- scratch (device globals) -----------------------------
__device__ float g_xT   [NB][LL][DM];        // transposed input x
__device__ float g_xz   [2][NB][LL][2*DI];   // in-proj output: [0..767]=xi, [768..1535]=z
__device__ float g_xc   [2][NB][LL][DI];     // after causal conv + silu
__device__ float g_xdbl [2][NB][LL][XW];     // x-proj output (dt | B | C)
__device__ float g_delta[2][NB][LL][DI];     // softplus(dt@dtw+b); later reused as gate output
__device__ float g_du   [2][NB][LL][DI];     // delta * xc
__device__ float g_Bc   [2][NB][LL/4][DS][4];// B repacked [t/4][n][t%4]
__device__ float g_Cc   [2][NB][LL/4][DS][4];
__device__ float g_y    [2][NB][LL][DI];     // scan output
__device__ float g_ycat [NB][LL][2*DM];      // concat(yf, yb) rows (b,t)
__device__ float g_yc   [NB][LL][2*DM];      // after final 1x1 conv + bias
__device__ float g_glu  [NB][LL][DM];        // a * sigmoid(b)
__device__ float2 g_part[NB][64];
__device__ float2 g_stats[NB];

// ----------------------------- helpers -----------------------------
__device__ __forceinline__ uint32_t smem_to_u32(const void* p) {
    uint32_t a;
    asm("{ .reg .u64 t; cvta.to.shared.u64 t, %1; cvt.u32.u64 %0, t; }" : "=r"(a) : "l"(p));
    return a;
}
#define CVT_BF16X2_F32(result, a, b) \
    asm("cvt.rn.satfinite.bf16x2.f32 %0, %1, %2;" : "=r"(result) : "f"(b), "f"(a))

__device__ __forceinline__ void sts64(uint32_t a, uint32_t x, uint32_t y){
    asm volatile("st.shared.v2.b32 [%0], {%1, %2};" :: "r"(a), "r"(x), "r"(y));
}
__device__ __forceinline__ void ldsm4(uint32_t* r, uint32_t addr){
    asm volatile("ldmatrix.sync.aligned.m8n8.x4.shared.b16 {%0,%1,%2,%3}, [%4];"
        : "=r"(r[0]), "=r"(r[1]), "=r"(r[2]), "=r"(r[3]) : "r"(addr));
}
__device__ __forceinline__ void mma_bf16(float* c, const uint32_t* a, const uint32_t* b){
    asm volatile("mma.sync.aligned.m16n8k16.row.col.f32.bf16.bf16.f32 "
        "{%0,%1,%2,%3}, {%4,%5,%6,%7}, {%8,%9}, {%0,%1,%2,%3};"
        : "+f"(c[0]), "+f"(c[1]), "+f"(c[2]), "+f"(c[3])
        : "r"(a[0]), "r"(a[1]), "r"(a[2]), "r"(a[3]), "r"(b[0]), "r"(b[1]));
}
// split fp32 quad into bf16 hi pair-packed and lo pair-packed
__device__ __forceinline__ void split4(float4 v, uint32_t &h0, uint32_t &h1, uint32_t &l0, uint32_t &l1){
    float hx = __bfloat162float(__float2bfloat16(v.x));
    float hy = __bfloat162float(__float2bfloat16(v.y));
    float hz = __bfloat162float(__float2bfloat16(v.z));
    float hw = __bfloat162float(__float2bfloat16(v.w));
    CVT_BF16X2_F32(h0, v.x, v.y);
    CVT_BF16X2_F32(h1, v.z, v.w);
    CVT_BF16X2_F32(l0, v.x - hx, v.y - hy);
    CVT_BF16X2_F32(l1, v.z - hz, v.w - hw);
}

// ===========================================================================
// HMMA GEMM (mma.sync bf16, 3-term hi/lo split), tile 128x64, K-chunk 64.
// A fp32 row-major [.][lda] (+optional row reversal), W fp32 [N][K], C fp32.
// mode 0 (inproj): z=dir*2+b -> A+(z&1)*Az, rev=z>>1, W=(z>>1)?W1:W0
// mode 1: A+z*Az, rev=0, W=z?W1:W0
// ===========================================================================
#define SM_AHI 0u
#define SM_ALO 16384u
#define SM_WHI 32768u
#define SM_WLO 40960u

__global__ __launch_bounds__(256, 2) void hmma_gemm(
    const float* __restrict__ A, int lda, long Az,
    const float* __restrict__ W0, const float* __restrict__ W1,
    const float* __restrict__ bias,
    float* __restrict__ C, int ldc, long Cz,
    int K, int mode)
{
    __shared__ __align__(16) char sm[49152];
    const uint32_t sb = smem_to_u32(sm);

    const int tid  = threadIdx.x;
    const int lane = tid & 31;
    const int warp = tid >> 5;
    const int m0w = (warp >> 1) * 32;   // warp tile row within CTA tile
    const int n0w = (warp & 1) * 32;    // warp tile col

    const int z = blockIdx.z;
    const int row0 = blockIdx.y * 128;
    const int col0 = blockIdx.x * 64;

    const float* Ab;
    int rev;
    const float* W;
    if (mode == 0) { Ab = A + (long)(z & 1) * Az; rev = z >> 1; W = (z >> 1) ? W1 : W0; }
    else           { Ab = A + (long)z * Az;       rev = 0;      W = z ? W1 : W0; }
    float* Cb = C + (long)z * Cz;

    float acc[2][4][4];
    #pragma unroll
    for (int i = 0; i < 2; i++)
        #pragma unroll
        for (int j = 0; j < 4; j++)
            #pragma unroll
            for (int q = 0; q < 4; q++) acc[i][j][q] = 0.f;

    // ldmatrix lane-address helpers (row-major, 128B rows, XOR-16B swizzle)
    const int lj = lane >> 3;     // matrix index 0..3
    const int lr = lane & 7;      // row within 8x8

    const int nc = K >> 6;
    for (int c = 0; c < nc; c++) {
        const int k0 = c << 6;
        // ---- gmem loads into regs (before sync: overlap with prior compute) ----
        float4 av[8], wv[4];
        {
            const int r = tid >> 4, c4 = tid & 15;   // base; i adds 16 rows
            #pragma unroll
            for (int i = 0; i < 8; i++) {
                int rr = r + i * 16;
                int ar = rev ? (LL - 1 - (row0 + rr)) : (row0 + rr);
                av[i] = *(const float4*)&Ab[(long)ar * lda + k0 + c4 * 4];
            }
            #pragma unroll
            for (int i = 0; i < 4; i++) {
                int rr = r + i * 16;
                wv[i] = *(const float4*)&W[(long)(col0 + rr) * K + k0 + c4 * 4];
            }
        }
        __syncthreads();   // prior compute done reading smem
        {
            const int r = tid >> 4, c4 = tid & 15;
            #pragma unroll
            for (int i = 0; i < 8; i++) {
                int rr = r + i * 16;
                uint32_t h0, h1, l0, l1; split4(av[i], h0, h1, l0, l1);
                uint32_t off = (uint32_t)(rr * 128 + c4 * 8);
                off ^= (uint32_t)((rr & 7) << 4);
                sts64(sb + SM_AHI + off, h0, h1);
                sts64(sb + SM_ALO + off, l0, l1);
            }
            #pragma unroll
            for (int i = 0; i < 4; i++) {
                int rr = r + i * 16;
                uint32_t h0, h1, l0, l1; split4(wv[i], h0, h1, l0, l1);
                uint32_t off = (uint32_t)(rr * 128 + c4 * 8);
                off ^= (uint32_t)((rr & 7) << 4);
                sts64(sb + SM_WHI + off, h0, h1);
                sts64(sb + SM_WLO + off, l0, l1);
            }
        }
        __syncthreads();
        // ---- compute: 4 k16 steps ----
        #pragma unroll
        for (int ks = 0; ks < 4; ks++) {
            const int kb = ks * 16;
            // A lane address: matrices [rows0-7,klo][rows8-15,klo][rows0-7,khi][rows8-15,khi]
            uint32_t ah[2][4], al[2][4];
            #pragma unroll
            for (int mh = 0; mh < 2; mh++) {
                int row = m0w + mh * 16 + ((lj & 1) << 3) + lr;
                int kc  = kb + ((lj >> 1) << 3);
                uint32_t off = (uint32_t)(row * 128 + kc * 2);
                off ^= (uint32_t)((row & 7) << 4);
                ldsm4(ah[mh], sb + SM_AHI + off);
                ldsm4(al[mh], sb + SM_ALO + off);
            }
            // B lane address: matrices [n0-7,klo][n0-7,khi][n8-15,klo][n8-15,khi]
            uint32_t bh[2][4], bl[2][4];
            #pragma unroll
            for (int np = 0; np < 2; np++) {
                int row = n0w + np * 16 + ((lj >> 1) << 3) + lr;
                int kc  = kb + ((lj & 1) << 3);
                uint32_t off = (uint32_t)(row * 128 + kc * 2);
                off ^= (uint32_t)((row & 7) << 4);
                ldsm4(bh[np], sb + SM_WHI + off);
                ldsm4(bl[np], sb + SM_WLO + off);
            }
            #pragma unroll
            for (int mh = 0; mh < 2; mh++) {
                #pragma unroll
                for (int ng = 0; ng < 4; ng++) {
                    const uint32_t* bph = &bh[ng >> 1][(ng & 1) * 2];
                    const uint32_t* bpl = &bl[ng >> 1][(ng & 1) * 2];
                    mma_bf16(acc[mh][ng], ah[mh], bph);
                    mma_bf16(acc[mh][ng], ah[mh], bpl);
                    mma_bf16(acc[mh][ng], al[mh], bph);
                }
            }
        }
    }

    // ---- epilogue: fragment -> gmem (float2 stores, optional bias) ----
    const int g = lane >> 2, tig = lane & 3;
    #pragma unroll
    for (int mh = 0; mh < 2; mh++) {
        #pragma unroll
        for (int ng = 0; ng < 4; ng++) {
            int row = row0 + m0w + mh * 16 + g;
            int col = col0 + n0w + ng * 8 + tig * 2;
            float b0 = 0.f, b1 = 0.f;
            if (bias) { b0 = bias[col]; b1 = bias[col + 1]; }
            float2 v0 = make_float2(acc[mh][ng][0] + b0, acc[mh][ng][1] + b1);
            float2 v1 = make_float2(acc[mh][ng][2] + b0, acc[mh][ng][3] + b1);
            *(float2*)&Cb[(long)row * ldc + col] = v0;
            *(float2*)&Cb[(long)(row + 8) * ldc + col] = v1;
        }
    }
}

// ----------------------------- x transpose: [b][c][t] -> [b][t][c] -----------------------------
__global__ __launch_bounds__(256) void transpose_x(const float* __restrict__ x)
{
    __shared__ float s[32][33];
    const int b = blockIdx.z;
    const int t0 = blockIdx.x * 32;
    const int c0 = blockIdx.y * 32;
    const int tx = threadIdx.x & 31;
    const int ty = threadIdx.x >> 5;
    #pragma unroll
    for (int j = 0; j < 4; j++)
        s[ty + j*8][tx] = x[((long)b * DM + c0 + ty + j*8) * LL + t0 + tx];
    __syncthreads();
    #pragma unroll
    for (int j = 0; j < 4; j++)
        g_xT[b][t0 + ty + j*8][c0 + tx] = s[tx][ty + j*8];
}

// ----------------------------- f32x2 helpers (small GEMMs) -----------------------------
__device__ __forceinline__ unsigned long long dup2(float x){
    unsigned long long r; asm("mov.b64 %0, {%1, %1};" : "=l"(r) : "f"(x)); return r;
}
__device__ __forceinline__ void ffma2(unsigned long long &d, unsigned long long a, unsigned long long b){
    asm("fma.rn.f32x2 %0, %1, %2, %0;" : "+l"(d) : "l"(a), "l"(b));
}
__device__ __forceinline__ float2 unpk2(unsigned long long v){
    float2 f; asm("mov.b64 {%0, %1}, %2;" : "=f"(f.x), "=f"(f.y) : "l"(v)); return f;
}

// ===========================================================================
// GEMM 128x64 tile, 8x4 microtile, f32x2 (xproj only, N=56)
// ===========================================================================
__global__ __launch_bounds__(256) void gemm128(
    const float* __restrict__ A, int lda, long Az,
    const float* __restrict__ W0, const float* __restrict__ W1,
    const float* __restrict__ bias,
    float* __restrict__ C, int ldc, long Cz,
    int N, int K)
{
    __shared__ float As[16][128];
    __shared__ float Bs[16][64];
    const int z = blockIdx.z;
    const float* Ab = A + (long)z * Az;
    const float* W  = (z == 0) ? W0 : W1;
    float* Cb = C + (long)z * Cz;
    const int row0 = blockIdx.y * 128;
    const int col0 = blockIdx.x * 64;
    const int tid = threadIdx.x;
    const int tx = tid & 15, ty = tid >> 4;

    const int am = tid & 127;
    const int akq = tid >> 7;
    const int wn = tid & 63;
    const int wkq = tid >> 6;
    const bool wok = (col0 + wn) < N;

    unsigned long long acc[4][4];
    #pragma unroll
    for (int i = 0; i < 4; i++)
        #pragma unroll
        for (int j = 0; j < 4; j++) acc[i][j] = 0ull;

    for (int k0 = 0; k0 < K; k0 += 16) {
        {
            const float* ar = &Ab[(long)(row0 + am) * lda + k0 + akq * 8];
            float4 v0 = *(const float4*)ar;
            float4 v1 = *(const float4*)(ar + 4);
            As[akq*8+0][am] = v0.x; As[akq*8+1][am] = v0.y;
            As[akq*8+2][am] = v0.z; As[akq*8+3][am] = v0.w;
            As[akq*8+4][am] = v1.x; As[akq*8+5][am] = v1.y;
            As[akq*8+6][am] = v1.z; As[akq*8+7][am] = v1.w;
        }
        {
            float4 v = make_float4(0.f, 0.f, 0.f, 0.f);
            if (wok) v = *(const float4*)&W[(long)(col0 + wn) * K + k0 + wkq * 4];
            Bs[wkq*4+0][wn] = v.x; Bs[wkq*4+1][wn] = v.y;
            Bs[wkq*4+2][wn] = v.z; Bs[wkq*4+3][wn] = v.w;
        }
        __syncthreads();
        #pragma unroll
        for (int k = 0; k < 16; k++) {
            unsigned long long a01 = *(const unsigned long long*)&As[k][ty*8];
            unsigned long long a23 = *(const unsigned long long*)&As[k][ty*8+2];
            unsigned long long a45 = *(const unsigned long long*)&As[k][ty*8+4];
            unsigned long long a67 = *(const unsigned long long*)&As[k][ty*8+6];
            float4 bv = *(const float4*)&Bs[k][tx*4];
            unsigned long long b0 = dup2(bv.x), b1 = dup2(bv.y), b2 = dup2(bv.z), b3 = dup2(bv.w);
            ffma2(acc[0][0], a01, b0); ffma2(acc[0][1], a01, b1);
            ffma2(acc[0][2], a01, b2); ffma2(acc[0][3], a01, b3);
            ffma2(acc[1][0], a23, b0); ffma2(acc[1][1], a23, b1);
            ffma2(acc[1][2], a23, b2); ffma2(acc[1][3], a23, b3);
            ffma2(acc[2][0], a45, b0); ffma2(acc[2][1], a45, b1);
            ffma2(acc[2][2], a45, b2); ffma2(acc[2][3], a45, b3);
            ffma2(acc[3][0], a67, b0); ffma2(acc[3][1], a67, b1);
            ffma2(acc[3][2], a67, b2); ffma2(acc[3][3], a67, b3);
        }
        __syncthreads();
    }
    const int colb = col0 + tx*4;
    float bsv[4] = {0.f, 0.f, 0.f, 0.f};
    if (bias) {
        #pragma unroll
        for (int j = 0; j < 4; j++) if (colb + j < N) bsv[j] = bias[colb + j];
    }
    #pragma unroll
    for (int p = 0; p < 4; p++) {
        float2 f0 = unpk2(acc[p][0]), f1 = unpk2(acc[p][1]);
        float2 f2 = unpk2(acc[p][2]), f3 = unpk2(acc[p][3]);
        long r0 = (long)(row0 + ty*8 + 2*p) * ldc;
        long r1 = r0 + ldc;
        if (colb + 3 < N) {
            *(float4*)&Cb[r0 + colb] = make_float4(f0.x+bsv[0], f1.x+bsv[1], f2.x+bsv[2], f3.x+bsv[3]);
            *(float4*)&Cb[r1 + colb] = make_float4(f0.y+bsv[0], f1.y+bsv[1], f2.y+bsv[2], f3.y+bsv[3]);
        } else {
            float o0[4] = {f0.x, f1.x, f2.x, f3.x};
            float o1[4] = {f0.y, f1.y, f2.y, f3.y};
            #pragma unroll
            for (int j = 0; j < 4; j++) if (colb + j < N) {
                Cb[r0 + colb + j] = o0[j] + bsv[j];
                Cb[r1 + colb + j] = o1[j] + bsv[j];
            }
        }
    }
}

// ===========================================================================
// delta GEMM: delta = softplus(dt @ dtw^T + dtb); du = delta * xc
// ===========================================================================
__global__ __launch_bounds__(256) void delta_gemm(
    const float* __restrict__ dtw0, const float* __restrict__ dtb0,
    const float* __restrict__ dtw1, const float* __restrict__ dtb1)
{
    __shared__ float As[DR][64];
    __shared__ float Bs[DR][64];
    const int dir = blockIdx.z;
    const float* Ab  = &g_xdbl[dir][0][0][0];
    const float* xcb = &g_xc[dir][0][0][0];
    float* pdl = &g_delta[dir][0][0][0];
    float* pdu = &g_du[dir][0][0][0];
    const float* dtw = dir ? dtw1 : dtw0;
    const float* dtb = dir ? dtb1 : dtb0;
    const int row0 = blockIdx.y * 64;
    const int col0 = blockIdx.x * 64;
    const int tid = threadIdx.x;
    const int tx = tid & 15, ty = tid >> 4;

    for (int i = tid; i < 64 * DR; i += 256) {
        int r = i / DR, k = i % DR;
        As[k][r] = Ab[(long)(row0 + r) * XW + k];
        Bs[k][r] = dtw[(long)(col0 + r) * DR + k];
    }
    __syncthreads();

    unsigned long long acc[2][4];
    #pragma unroll
    for (int i = 0; i < 2; i++)
        #pragma unroll
        for (int j = 0; j < 4; j++) acc[i][j] = 0ull;

    #pragma unroll
    for (int k = 0; k < DR; k++) {
        unsigned long long a01 = *(const unsigned long long*)&As[k][ty*4];
        unsigned long long a23 = *(const unsigned long long*)&As[k][ty*4+2];
        float4 bv = *(const float4*)&Bs[k][tx*4];
        unsigned long long b0 = dup2(bv.x), b1 = dup2(bv.y), b2 = dup2(bv.z), b3 = dup2(bv.w);
        ffma2(acc[0][0], a01, b0); ffma2(acc[0][1], a01, b1);
        ffma2(acc[0][2], a01, b2); ffma2(acc[0][3], a01, b3);
        ffma2(acc[1][0], a23, b0); ffma2(acc[1][1], a23, b1);
        ffma2(acc[1][2], a23, b2); ffma2(acc[1][3], a23, b3);
    }
    const int colb = col0 + tx*4;
    float4 bias4 = *(const float4*)&dtb[colb];
    float bsv[4] = {bias4.x, bias4.y, bias4.z, bias4.w};
    float out[4][4];
    #pragma unroll
    for (int i = 0; i < 2; i++)
        #pragma unroll
        for (int j = 0; j < 4; j++) {
            float2 f = unpk2(acc[i][j]);
            out[2*i][j] = f.x; out[2*i+1][j] = f.y;
        }
    #pragma unroll
    for (int r = 0; r < 4; r++) {
        long row = row0 + ty*4 + r;
        float4 xc4 = *(const float4*)&xcb[row * DI + colb];
        float xcv[4] = {xc4.x, xc4.y, xc4.z, xc4.w};
        float dl[4], du[4];
        #pragma unroll
        for (int j = 0; j < 4; j++) {
            float s = out[r][j] + bsv[j];
            float sp = fmaxf(s, 0.f) + log1pf(__expf(-fabsf(s)));
            dl[j] = sp;
            du[j] = sp * xcv[j];
        }
        *(float4*)&pdl[row * DI + colb] = make_float4(dl[0], dl[1], dl[2], dl[3]);
        *(float4*)&pdu[row * DI + colb] = make_float4(du[0], du[1], du[2], du[3]);
    }
}

// ----------------------------- B/C repack -----------------------------
__global__ __launch_bounds__(256) void repack_kernel()
{
    int id = blockIdx.x * 256 + threadIdx.x;
    if (id >= 2 * NB * LL * 2 * DS) return;
    int n = id & 15;
    int which = (id >> 4) & 1;
    int t = (id >> 5) & (LL - 1);
    int b = (id >> 17) & 1;
    int dir = (id >> 18) & 1;
    float v = g_xdbl[dir][b][t][DR + which * DS + n];
    float* dst = which ? &g_Cc[dir][b][0][0][0] : &g_Bc[dir][b][0][0][0];
    dst[(t >> 2) * (DS*4) + n * 4 + (t & 3)] = v;
}

// ----------------------------- depthwise causal conv + silu -----------------------------
__global__ __launch_bounds__(256) void conv_silu_kernel(
    const float* __restrict__ cw0, const float* __restrict__ cb0,
    const float* __restrict__ cw1, const float* __restrict__ cb1)
{
    long id = (long)blockIdx.x * 256 + threadIdx.x;
    const long total = (long)2 * NB * LL * DI;
    if (id >= total) return;
    int d = (int)(id % DI); long r = id / DI;
    int t = (int)(r % LL); r /= LL;
    int b = (int)(r % NB); int dir = (int)(r / NB);
    const float* cw = dir ? cw1 : cw0;
    const float* cb = dir ? cb1 : cb0;
    const float* xi = &g_xz[dir][b][0][0];
    float acc = cb[d];
    #pragma unroll
    for (int i = 0; i < 4; i++) {
        int tt = t - 3 + i;
        if (tt >= 0) acc += cw[d*4 + i] * xi[(long)tt * (2*DI) + d];
    }
    g_xc[dir][b][t][d] = acc / (1.f + __expf(-acc));
}

// ----------------------------- selective scan: thread = (dir,b,d,n) -----------------------------
__global__ __launch_bounds__(256) void scan_kernel(
    const float* __restrict__ Al0, const float* __restrict__ Al1)
{
    const int gid = blockIdx.x * 256 + threadIdx.x;
    const int n  = gid & 15;
    const int cj = gid >> 4;
    const int dir = cj / (NB * DI);
    const int rem = cj % (NB * DI);
    const int b = rem / DI;
    const int d = rem % DI;
    const float* Al = dir ? Al1 : Al0;
    const float Acoef = -__expf(Al[d*DS + n]);
    const float*  pd = &g_delta[dir][b][0][0];
    const float*  pu = &g_du[dir][b][0][0];
    const float4* pB = (const float4*)&g_Bc[dir][b][0][0][0];
    const float4* pC = (const float4*)&g_Cc[dir][b][0][0][0];
    float* py = &g_y[dir][b][0][0];
    float h = 0.f;
    float4 Bv = __ldg(&pB[n]);
    float4 Cv = __ldg(&pC[n]);
    for (int t4 = 0; t4 < LL/4; t4++) {
        float4 Bn = make_float4(0.f,0.f,0.f,0.f), Cn = Bn;
        if (t4 + 1 < LL/4) {
            Bn = __ldg(&pB[(t4+1)*16 + n]);
            Cn = __ldg(&pC[(t4+1)*16 + n]);
        }
        float dl[4], uu[4];
        #pragma unroll
        for (int j = 0; j < 4; j++) {
            long o = (long)(t4*4 + j) * DI + d;
            dl[j] = __ldg(pd + o);
            uu[j] = __ldg(pu + o);
        }
        float dA[4];
        #pragma unroll
        for (int j = 0; j < 4; j++) dA[j] = __expf(dl[j] * Acoef);
        #pragma unroll
        for (int j = 0; j < 4; j++) {
            int t = t4*4 + j;
            float Bj = (j==0) ? Bv.x : (j==1) ? Bv.y : (j==2) ? Bv.z : Bv.w;
            float Cj = (j==0) ? Cv.x : (j==1) ? Cv.y : (j==2) ? Cv.z : Cv.w;
            h = fmaf(dA[j], h, uu[j] * Bj);
            float p = h * Cj;
            p += __shfl_xor_sync(0xffffffffu, p, 1);
            p += __shfl_xor_sync(0xffffffffu, p, 2);
            p += __shfl_xor_sync(0xffffffffu, p, 4);
            p += __shfl_xor_sync(0xffffffffu, p, 8);
            if (n == 0) py[(long)t*DI + d] = p;
        }
        Bv = Bn; Cv = Cn;
    }
}

// ----------------------------- gate: (y + xc*D) * silu(z) -----------------------------
__global__ __launch_bounds__(256) void gate_kernel(
    const float* __restrict__ D0, const float* __restrict__ D1)
{
    long id = (long)blockIdx.x * 256 + threadIdx.x;
    const long total = (long)2 * NB * LL * DI;
    if (id >= total) return;
    int d = (int)(id % DI); long r = id / DI;
    int t = (int)(r % LL); r /= LL;
    int b = (int)(r % NB); int dir = (int)(r / NB);
    float Dp = (dir ? D1 : D0)[d];
    float y = g_y[dir][b][t][d] + g_xc[dir][b][t][d] * Dp;
    float z = g_xz[dir][b][t][DI + d];
    float sz = z / (1.f + __expf(-z));
    g_delta[dir][b][t][d] = y * sz;
}

// ----------------------------- GLU + partial stats -----------------------------
__global__ __launch_bounds__(256) void glu_kernel()
{
    const int batch = blockIdx.y;
    const int tid = threadIdx.x;
    float lsum = 0.f, lssq = 0.f;
    const float* yc = &g_yc[batch][0][0];
    float* gl = &g_glu[batch][0][0];
    for (int it = 0; it < 128; it++) {
        long e = (long)blockIdx.x * 32768 + (long)it * 256 + tid;
        int t = (int)(e / DM), o = (int)(e % DM);
        float a  = yc[(long)t * (2*DM) + o];
        float bg = yc[(long)t * (2*DM) + DM + o];
        float g = a * (1.f / (1.f + __expf(-bg)));
        gl[e] = g;
        lsum += g; lssq += g * g;
    }
    __shared__ float s1[256], s2[256];
    s1[tid] = lsum; s2[tid] = lssq;
    __syncthreads();
    for (int s = 128; s > 0; s >>= 1) {
        if (tid < s) { s1[tid] += s1[tid+s]; s2[tid] += s2[tid+s]; }
        __syncthreads();
    }
    if (tid == 0) g_part[batch][blockIdx.x] = make_float2(s1[0], s2[0]);
}

__global__ void stats_kernel()
{
    int b = threadIdx.x;
    if (b < NB) {
        float sum = 0.f, ssq = 0.f;
        for (int i = 0; i < 48; i++) { float2 p = g_part[b][i]; sum += p.x; ssq += p.y; }
        const float inv = 1.f / ((float)DM * (float)LL);
        float mu = sum * inv;
        float var = ssq * inv - mu * mu;
        g_stats[b] = make_float2(mu, rsqrtf(var + 1e-5f));
    }
}

// ----------------------------- normalize + transpose to output [b][c][t] -----------------------------
__global__ __launch_bounds__(256) void norm_kernel(
    const float* __restrict__ gnw, const float* __restrict__ gnb,
    float* __restrict__ out)
{
    __shared__ float s[32][33];
    const int b = blockIdx.z;
    const int t0 = blockIdx.x * 32;
    const int c0 = blockIdx.y * 32;
    const int tx = threadIdx.x & 31;
    const int ty = threadIdx.x >> 5;
    #pragma unroll
    for (int j = 0; j < 4; j++) {
        int t = t0 + ty + j*8;
        s[ty + j*8][tx] = g_glu[b][t][c0 + tx];
    }
    __syncthreads();
    float2 st = g_stats[b];
    #pragma unroll
    for (int j = 0; j < 4; j++) {
        int c = c0 + ty + j*8;
        float v = s[tx][ty + j*8];
        out[((long)b * DM + c) * LL + t0 + tx] = (v - st.x) * st.y * gnw[c] + gnb[c];
    }
}

// ----------------------------- launch -----------------------------
extern "C" void kernel_launch(void* const* d_in, const int* in_sizes, int n_in,
                              void* d_out, int out_size)
{
    (void)in_sizes; (void)n_in; (void)out_size;
    const float* x        = (const float*)d_in[0];
    const float* f_in_w   = (const float*)d_in[1];
    const float* f_conv_w = (const float*)d_in[2];
    const float* f_conv_b = (const float*)d_in[3];
    const float* f_xproj  = (const float*)d_in[4];
    const float* f_dt_w   = (const float*)d_in[5];
    const float* f_dt_b   = (const float*)d_in[6];
    const float* f_A_log  = (const float*)d_in[7];
    const float* f_D      = (const float*)d_in[8];
    const float* f_out_w  = (const float*)d_in[9];
    const float* b_in_w   = (const float*)d_in[10];
    const float* b_conv_w = (const float*)d_in[11];
    const float* b_conv_b = (const float*)d_in[12];
    const float* b_xproj  = (const float*)d_in[13];
    const float* b_dt_w   = (const float*)d_in[14];
    const float* b_dt_b   = (const float*)d_in[15];
    const float* b_A_log  = (const float*)d_in[16];
    const float* b_D      = (const float*)d_in[17];
    const float* b_out_w  = (const float*)d_in[18];
    const float* c_w      = (const float*)d_in[19];
    const float* c_b      = (const float*)d_in[20];
    const float* gn_w     = (const float*)d_in[21];
    const float* gn_b     = (const float*)d_in[22];
    float* out = (float*)d_out;

    float *pxT, *pxz, *pxc, *pxdbl, *pgate, *pycat, *pyc;
    cudaGetSymbolAddress((void**)&pxT,   g_xT);
    cudaGetSymbolAddress((void**)&pxz,   g_xz);
    cudaGetSymbolAddress((void**)&pxc,   g_xc);
    cudaGetSymbolAddress((void**)&pxdbl, g_xdbl);
    cudaGetSymbolAddress((void**)&pgate, g_delta);   // reused as gate output
    cudaGetSymbolAddress((void**)&pycat, g_ycat);
    cudaGetSymbolAddress((void**)&pyc,   g_yc);

    // 0) transpose x -> xT[b][t][c]
    transpose_x<<<dim3(LL/32, DM/32, NB), 256>>>(x);

    // 1) in-projection (HMMA): per z=dir*2+b, M=4096, N=1536, K=384
    hmma_gemm<<<dim3(24, 32, 4), 256>>>(
        pxT, DM, (long)LL*DM,
        f_in_w, b_in_w, nullptr,
        pxz, 2*DI, (long)LL*2*DI,
        DM, 0);

    // 2) depthwise causal conv + silu
    {
        long total = (long)2 * NB * LL * DI;
        conv_silu_kernel<<<(unsigned)((total + 255) / 256), 256>>>(f_conv_w, f_conv_b, b_conv_w, b_conv_b);
    }

    // 3) x-projection -> xdbl (N=56, f32x2 path)
    gemm128<<<dim3(1, (NB*LL)/128, 2), 256>>>(
        pxc, DI, (long)NB*LL*DI,
        f_xproj, b_xproj, nullptr,
        pxdbl, XW, (long)NB*LL*XW,
        XW, DI);

    // 4) delta = softplus(dt @ dtw^T + dtb), du = delta*xc
    delta_gemm<<<dim3(DI/64, (NB*LL)/64, 2), 256>>>(f_dt_w, f_dt_b, b_dt_w, b_dt_b);

    // 4b) repack B/C for scan
    repack_kernel<<<2048, 256>>>();

    // 5) selective scan
    scan_kernel<<<192, 256>>>(f_A_log, b_A_log);

    // 6) gate
    {
        long total = (long)2 * NB * LL * DI;
        gate_kernel<<<(unsigned)((total + 255) / 256), 256>>>(f_D, b_D);
    }

    // 7) out-projection (HMMA): per dir, M=8192, N=384, K=768 -> ycat col half
    hmma_gemm<<<dim3(6, 64, 2), 256>>>(
        pgate, DI, (long)NB*LL*DI,
        f_out_w, b_out_w, nullptr,
        pycat, 2*DM, (long)DM,
        DI, 1);

    // 8) final 1x1 conv (HMMA): M=8192, N=768, K=768, bias
    hmma_gemm<<<dim3(12, 64, 1), 256>>>(
        pycat, 2*DM, 0L,
        c_w, c_w, c_b,
        pyc, 2*DM, 0L,
        2*DM, 1);

    // 9) GLU + partial stats; 10) stats; 11) normalize + transpose out
    glu_kernel<<<dim3(48, 2), 256>>>();
    stats_kernel<<<1, 32>>>();
    norm_kernel<<<dim3(LL/32, DM/32, NB), 256>>>(gn_w, gn_b, out);
}

// round 8
// speedup vs baseline: 1.5944x; 1.0563x over previous
#include <cuda_runtime.h>
#include <cuda_bf16.h>
#include <cstdint>

#define LL 4096
#define DM 384
#define DI 768
#define DS 16
#define DR 24
#define NB 2
#define XW (DR + 2*DS)   // 56

// ----------------------------- scratch (device globals) -----------------------------
__device__ float g_xz   [2][NB][LL][2*DI];   // in-proj output: [0..767]=xi, [768..1535]=z
__device__ float g_xc   [2][NB][LL][DI];     // after causal conv + silu
__device__ float g_xdbl [2][NB][LL][XW];     // x-proj output (dt | B | C)
__device__ float g_delta[2][NB][LL][DI];     // softplus(dt@dtw+b)
__device__ float g_du   [2][NB][LL][DI];     // delta * xc
__device__ float g_Bc   [2][NB][LL/4][DS][4];// B repacked [t/4][n][t%4]
__device__ float g_Cc   [2][NB][LL/4][DS][4];
__device__ float g_y    [2][NB][LL][DI];     // scan output
__device__ float g_yc   [NB][LL][2*DM];      // after final 1x1 conv + bias
__device__ float g_glu  [NB][LL][DM];        // a * sigmoid(b)
__device__ float2 g_part[NB][64];
__device__ float2 g_stats[NB];

// bf16 hi/lo operand buffers for HMMA GEMMs
__device__ __align__(16) __nv_bfloat16 g_xT_hi  [NB][LL][DM];
__device__ __align__(16) __nv_bfloat16 g_xT_lo  [NB][LL][DM];
__device__ __align__(16) __nv_bfloat16 g_inw_hi [2][2*DI][DM];
__device__ __align__(16) __nv_bfloat16 g_inw_lo [2][2*DI][DM];
__device__ __align__(16) __nv_bfloat16 g_gate_hi[2][NB][LL][DI];
__device__ __align__(16) __nv_bfloat16 g_gate_lo[2][NB][LL][DI];
__device__ __align__(16) __nv_bfloat16 g_outw_hi[2][DM][DI];
__device__ __align__(16) __nv_bfloat16 g_outw_lo[2][DM][DI];
__device__ __align__(16) __nv_bfloat16 g_ycat_hi[NB][LL][2*DM];
__device__ __align__(16) __nv_bfloat16 g_ycat_lo[NB][LL][2*DM];
__device__ __align__(16) __nv_bfloat16 g_cw_hi  [2*DM][2*DM];
__device__ __align__(16) __nv_bfloat16 g_cw_lo  [2*DM][2*DM];

// ----------------------------- helpers -----------------------------
__device__ __forceinline__ uint32_t smem_to_u32(const void* p) {
    uint32_t a;
    asm("{ .reg .u64 t; cvta.to.shared.u64 t, %1; cvt.u32.u64 %0, t; }" : "=r"(a) : "l"(p));
    return a;
}
__device__ __forceinline__ uint32_t packbf(float a, float b){   // a -> low half
    uint16_t x = __bfloat16_as_ushort(__float2bfloat16(a));
    uint16_t y = __bfloat16_as_ushort(__float2bfloat16(b));
    return ((uint32_t)y << 16) | x;
}
__device__ __forceinline__ void ldsm4(uint32_t* r, uint32_t addr){
    asm volatile("ldmatrix.sync.aligned.m8n8.x4.shared.b16 {%0,%1,%2,%3}, [%4];"
        : "=r"(r[0]), "=r"(r[1]), "=r"(r[2]), "=r"(r[3]) : "r"(addr));
}
__device__ __forceinline__ void mma_bf16(float* c, const uint32_t* a, const uint32_t* b){
    asm volatile("mma.sync.aligned.m16n8k16.row.col.f32.bf16.bf16.f32 "
        "{%0,%1,%2,%3}, {%4,%5,%6,%7}, {%8,%9}, {%0,%1,%2,%3};"
        : "+f"(c[0]), "+f"(c[1]), "+f"(c[2]), "+f"(c[3])
        : "r"(a[0]), "r"(a[1]), "r"(a[2]), "r"(a[3]), "r"(b[0]), "r"(b[1]));
}
__device__ __forceinline__ void cpasync16(uint32_t s, const void* g){
    asm volatile("cp.async.cg.shared.global [%0], [%1], 16;" :: "r"(s), "l"(g));
}
#define CP_COMMIT() asm volatile("cp.async.commit_group;" ::: "memory")
template<int N> __device__ __forceinline__ void cpwait(){
    asm volatile("cp.async.wait_group %0;" :: "n"(N) : "memory");
}

// ===========================================================================
// HMMA GEMM, operands pre-split bf16 hi/lo in gmem. Tile 128x64, K-chunk 64,
// cp.async double-buffered pipeline. 3-term product (ah*bh + ah*bl + al*bh).
// mode 0 inproj : z=dir*2+b; A+= (z&1)*Az; rev=z>>1; W=(z>>1)?W1:W0; fp32 out
// mode 1 outproj: z=dir;     A+= z*Az;     rev=0;    W=z?W1:W0;      bf16 hi/lo out
// mode 2 conv1x1: z=0;       W0; bias;                               fp32 out
// ===========================================================================
#define SM_AHI 0u
#define SM_ALO 16384u
#define SM_WHI 32768u
#define SM_WLO 40960u
#define SM_BUF 49152u
#define HMMA_SMEM (2 * SM_BUF)

__device__ __forceinline__ void load_chunk(
    uint32_t bufb,
    const __nv_bfloat16* __restrict__ Ahi, const __nv_bfloat16* __restrict__ Alo,
    const __nv_bfloat16* __restrict__ Whi, const __nv_bfloat16* __restrict__ Wlo,
    int lda, int ldw, int k0, int row0, int col0, int rev, int tid)
{
    #pragma unroll
    for (int i = 0; i < 4; i++) {
        int u = i * 256 + tid;
        int rr = u >> 3, c8 = u & 7;
        int ar = rev ? (LL - 1 - (row0 + rr)) : (row0 + rr);
        uint32_t off = ((uint32_t)(rr * 128 + c8 * 16)) ^ ((uint32_t)(rr & 7) << 4);
        long gs = (long)ar * lda + k0 + c8 * 8;
        cpasync16(bufb + SM_AHI + off, Ahi + gs);
        cpasync16(bufb + SM_ALO + off, Alo + gs);
    }
    #pragma unroll
    for (int i = 0; i < 2; i++) {
        int u = i * 256 + tid;
        int rr = u >> 3, c8 = u & 7;
        uint32_t off = ((uint32_t)(rr * 128 + c8 * 16)) ^ ((uint32_t)(rr & 7) << 4);
        long gs = (long)(col0 + rr) * ldw + k0 + c8 * 8;
        cpasync16(bufb + SM_WHI + off, Whi + gs);
        cpasync16(bufb + SM_WLO + off, Wlo + gs);
    }
}

__global__ __launch_bounds__(256, 2) void hmma_gemm(
    const __nv_bfloat16* __restrict__ Ahi, const __nv_bfloat16* __restrict__ Alo,
    int lda, long Az,
    const __nv_bfloat16* __restrict__ Whi0, const __nv_bfloat16* __restrict__ Wlo0,
    const __nv_bfloat16* __restrict__ Whi1, const __nv_bfloat16* __restrict__ Wlo1,
    const float* __restrict__ bias,
    float* __restrict__ Cf,
    __nv_bfloat16* __restrict__ Chi, __nv_bfloat16* __restrict__ Clo,
    int ldc, long Cz, int K, int mode)
{
    extern __shared__ __align__(16) char sm[];
    const uint32_t sb = smem_to_u32(sm);

    const int tid  = threadIdx.x;
    const int lane = tid & 31;
    const int warp = tid >> 5;
    const int m0w = (warp >> 1) * 32;
    const int n0w = (warp & 1) * 32;

    const int z = blockIdx.z;
    const int row0 = blockIdx.y * 128;
    const int col0 = blockIdx.x * 64;

    const __nv_bfloat16 *pAhi, *pAlo, *pWhi, *pWlo;
    int rev = 0;
    if (mode == 0) {
        pAhi = Ahi + (long)(z & 1) * Az; pAlo = Alo + (long)(z & 1) * Az;
        rev = z >> 1;
        pWhi = (z >> 1) ? Whi1 : Whi0;  pWlo = (z >> 1) ? Wlo1 : Wlo0;
    } else {
        pAhi = Ahi + (long)z * Az; pAlo = Alo + (long)z * Az;
        pWhi = z ? Whi1 : Whi0;    pWlo = z ? Wlo1 : Wlo0;
    }

    float acc[2][4][4];
    #pragma unroll
    for (int i = 0; i < 2; i++)
        #pragma unroll
        for (int j = 0; j < 4; j++)
            #pragma unroll
            for (int q = 0; q < 4; q++) acc[i][j][q] = 0.f;

    const int lj = lane >> 3;
    const int lr = lane & 7;
    const int nc = K >> 6;

    load_chunk(sb, pAhi, pAlo, pWhi, pWlo, lda, K, 0, row0, col0, rev, tid);
    CP_COMMIT();

    for (int c = 0; c < nc; c++) {
        if (c + 1 < nc) {
            load_chunk(sb + ((c + 1) & 1) * SM_BUF, pAhi, pAlo, pWhi, pWlo,
                       lda, K, (c + 1) << 6, row0, col0, rev, tid);
            CP_COMMIT();
            cpwait<1>();
        } else {
            cpwait<0>();
        }
        __syncthreads();
        const uint32_t bufb = sb + (c & 1) * SM_BUF;
        #pragma unroll
        for (int ks = 0; ks < 4; ks++) {
            const int kb = ks * 16;
            uint32_t ah[2][4], al[2][4];
            #pragma unroll
            for (int mh = 0; mh < 2; mh++) {
                int row = m0w + mh * 16 + ((lj & 1) << 3) + lr;
                int kc  = kb + ((lj >> 1) << 3);
                uint32_t off = ((uint32_t)(row * 128 + kc * 2)) ^ ((uint32_t)(row & 7) << 4);
                ldsm4(ah[mh], bufb + SM_AHI + off);
                ldsm4(al[mh], bufb + SM_ALO + off);
            }
            uint32_t bh[2][4], bl[2][4];
            #pragma unroll
            for (int np = 0; np < 2; np++) {
                int row = n0w + np * 16 + ((lj >> 1) << 3) + lr;
                int kc  = kb + ((lj & 1) << 3);
                uint32_t off = ((uint32_t)(row * 128 + kc * 2)) ^ ((uint32_t)(row & 7) << 4);
                ldsm4(bh[np], bufb + SM_WHI + off);
                ldsm4(bl[np], bufb + SM_WLO + off);
            }
            #pragma unroll
            for (int mh = 0; mh < 2; mh++) {
                #pragma unroll
                for (int ng = 0; ng < 4; ng++) {
                    const uint32_t* bph = &bh[ng >> 1][(ng & 1) * 2];
                    const uint32_t* bpl = &bl[ng >> 1][(ng & 1) * 2];
                    mma_bf16(acc[mh][ng], ah[mh], bph);
                    mma_bf16(acc[mh][ng], ah[mh], bpl);
                    mma_bf16(acc[mh][ng], al[mh], bph);
                }
            }
        }
        __syncthreads();
    }

    // ---- epilogue ----
    const int g = lane >> 2, tig = lane & 3;
    if (mode == 1) {
        uint32_t* Oh = (uint32_t*)(Chi + (long)z * Cz);
        uint32_t* Ol = (uint32_t*)(Clo + (long)z * Cz);
        #pragma unroll
        for (int mh = 0; mh < 2; mh++) {
            #pragma unroll
            for (int ng = 0; ng < 4; ng++) {
                int row = row0 + m0w + mh * 16 + g;
                int col = col0 + n0w + ng * 8 + tig * 2;
                #pragma unroll
                for (int hv = 0; hv < 2; hv++) {
                    float a0 = acc[mh][ng][hv*2], a1 = acc[mh][ng][hv*2+1];
                    float h0 = __bfloat162float(__float2bfloat16(a0));
                    float h1 = __bfloat162float(__float2bfloat16(a1));
                    long idx = ((long)(row + hv*8) * ldc + col) >> 1;
                    Oh[idx] = packbf(a0, a1);
                    Ol[idx] = packbf(a0 - h0, a1 - h1);
                }
            }
        }
    } else {
        float* Cb = Cf + (long)z * Cz;
        #pragma unroll
        for (int mh = 0; mh < 2; mh++) {
            #pragma unroll
            for (int ng = 0; ng < 4; ng++) {
                int row = row0 + m0w + mh * 16 + g;
                int col = col0 + n0w + ng * 8 + tig * 2;
                float b0 = 0.f, b1 = 0.f;
                if (bias) { b0 = bias[col]; b1 = bias[col + 1]; }
                *(float2*)&Cb[(long)row * ldc + col] =
                    make_float2(acc[mh][ng][0] + b0, acc[mh][ng][1] + b1);
                *(float2*)&Cb[(long)(row + 8) * ldc + col] =
                    make_float2(acc[mh][ng][2] + b0, acc[mh][ng][3] + b1);
            }
        }
    }
}

// ----------------------------- weight fp32 -> bf16 hi/lo -----------------------------
__global__ __launch_bounds__(256) void convert_pair(
    const float* __restrict__ src, __nv_bfloat16* __restrict__ hi,
    __nv_bfloat16* __restrict__ lo, int npairs)
{
    int i = blockIdx.x * 256 + threadIdx.x;
    if (i >= npairs) return;
    float2 v = *(const float2*)&src[i * 2];
    float h0 = __bfloat162float(__float2bfloat16(v.x));
    float h1 = __bfloat162float(__float2bfloat16(v.y));
    ((uint32_t*)hi)[i] = packbf(v.x, v.y);
    ((uint32_t*)lo)[i] = packbf(v.x - h0, v.y - h1);
}

// ----------------------------- x transpose: [b][c][t] -> bf16 hi/lo [b][t][c] -----------------------------
__global__ __launch_bounds__(256) void transpose_x(const float* __restrict__ x)
{
    __shared__ float s[32][33];
    const int b = blockIdx.z;
    const int t0 = blockIdx.x * 32;
    const int c0 = blockIdx.y * 32;
    const int tx = threadIdx.x & 31;
    const int ty = threadIdx.x >> 5;
    #pragma unroll
    for (int j = 0; j < 4; j++)
        s[ty + j*8][tx] = x[((long)b * DM + c0 + ty + j*8) * LL + t0 + tx];
    __syncthreads();
    #pragma unroll
    for (int j = 0; j < 4; j++) {
        int t = t0 + ty + j*8, c = c0 + tx;
        float v = s[tx][ty + j*8];
        __nv_bfloat16 h = __float2bfloat16(v);
        g_xT_hi[b][t][c] = h;
        g_xT_lo[b][t][c] = __float2bfloat16(v - __bfloat162float(h));
    }
}

// ----------------------------- f32x2 helpers (small GEMMs) -----------------------------
__device__ __forceinline__ unsigned long long dup2(float x){
    unsigned long long r; asm("mov.b64 %0, {%1, %1};" : "=l"(r) : "f"(x)); return r;
}
__device__ __forceinline__ void ffma2(unsigned long long &d, unsigned long long a, unsigned long long b){
    asm("fma.rn.f32x2 %0, %1, %2, %0;" : "+l"(d) : "l"(a), "l"(b));
}
__device__ __forceinline__ float2 unpk2(unsigned long long v){
    float2 f; asm("mov.b64 {%0, %1}, %2;" : "=f"(f.x), "=f"(f.y) : "l"(v)); return f;
}

// ===========================================================================
// GEMM 128x64 tile, 8x4 microtile, f32x2 (xproj only, N=56)
// ===========================================================================
__global__ __launch_bounds__(256) void gemm128(
    const float* __restrict__ A, int lda, long Az,
    const float* __restrict__ W0, const float* __restrict__ W1,
    const float* __restrict__ bias,
    float* __restrict__ C, int ldc, long Cz,
    int N, int K)
{
    __shared__ float As[16][128];
    __shared__ float Bs[16][64];
    const int z = blockIdx.z;
    const float* Ab = A + (long)z * Az;
    const float* W  = (z == 0) ? W0 : W1;
    float* Cb = C + (long)z * Cz;
    const int row0 = blockIdx.y * 128;
    const int col0 = blockIdx.x * 64;
    const int tid = threadIdx.x;
    const int tx = tid & 15, ty = tid >> 4;

    const int am = tid & 127;
    const int akq = tid >> 7;
    const int wn = tid & 63;
    const int wkq = tid >> 6;
    const bool wok = (col0 + wn) < N;

    unsigned long long acc[4][4];
    #pragma unroll
    for (int i = 0; i < 4; i++)
        #pragma unroll
        for (int j = 0; j < 4; j++) acc[i][j] = 0ull;

    for (int k0 = 0; k0 < K; k0 += 16) {
        {
            const float* ar = &Ab[(long)(row0 + am) * lda + k0 + akq * 8];
            float4 v0 = *(const float4*)ar;
            float4 v1 = *(const float4*)(ar + 4);
            As[akq*8+0][am] = v0.x; As[akq*8+1][am] = v0.y;
            As[akq*8+2][am] = v0.z; As[akq*8+3][am] = v0.w;
            As[akq*8+4][am] = v1.x; As[akq*8+5][am] = v1.y;
            As[akq*8+6][am] = v1.z; As[akq*8+7][am] = v1.w;
        }
        {
            float4 v = make_float4(0.f, 0.f, 0.f, 0.f);
            if (wok) v = *(const float4*)&W[(long)(col0 + wn) * K + k0 + wkq * 4];
            Bs[wkq*4+0][wn] = v.x; Bs[wkq*4+1][wn] = v.y;
            Bs[wkq*4+2][wn] = v.z; Bs[wkq*4+3][wn] = v.w;
        }
        __syncthreads();
        #pragma unroll
        for (int k = 0; k < 16; k++) {
            unsigned long long a01 = *(const unsigned long long*)&As[k][ty*8];
            unsigned long long a23 = *(const unsigned long long*)&As[k][ty*8+2];
            unsigned long long a45 = *(const unsigned long long*)&As[k][ty*8+4];
            unsigned long long a67 = *(const unsigned long long*)&As[k][ty*8+6];
            float4 bv = *(const float4*)&Bs[k][tx*4];
            unsigned long long b0 = dup2(bv.x), b1 = dup2(bv.y), b2 = dup2(bv.z), b3 = dup2(bv.w);
            ffma2(acc[0][0], a01, b0); ffma2(acc[0][1], a01, b1);
            ffma2(acc[0][2], a01, b2); ffma2(acc[0][3], a01, b3);
            ffma2(acc[1][0], a23, b0); ffma2(acc[1][1], a23, b1);
            ffma2(acc[1][2], a23, b2); ffma2(acc[1][3], a23, b3);
            ffma2(acc[2][0], a45, b0); ffma2(acc[2][1], a45, b1);
            ffma2(acc[2][2], a45, b2); ffma2(acc[2][3], a45, b3);
            ffma2(acc[3][0], a67, b0); ffma2(acc[3][1], a67, b1);
            ffma2(acc[3][2], a67, b2); ffma2(acc[3][3], a67, b3);
        }
        __syncthreads();
    }
    const int colb = col0 + tx*4;
    float bsv[4] = {0.f, 0.f, 0.f, 0.f};
    if (bias) {
        #pragma unroll
        for (int j = 0; j < 4; j++) if (colb + j < N) bsv[j] = bias[colb + j];
    }
    #pragma unroll
    for (int p = 0; p < 4; p++) {
        float2 f0 = unpk2(acc[p][0]), f1 = unpk2(acc[p][1]);
        float2 f2 = unpk2(acc[p][2]), f3 = unpk2(acc[p][3]);
        long r0 = (long)(row0 + ty*8 + 2*p) * ldc;
        long r1 = r0 + ldc;
        if (colb + 3 < N) {
            *(float4*)&Cb[r0 + colb] = make_float4(f0.x+bsv[0], f1.x+bsv[1], f2.x+bsv[2], f3.x+bsv[3]);
            *(float4*)&Cb[r1 + colb] = make_float4(f0.y+bsv[0], f1.y+bsv[1], f2.y+bsv[2], f3.y+bsv[3]);
        } else {
            float o0[4] = {f0.x, f1.x, f2.x, f3.x};
            float o1[4] = {f0.y, f1.y, f2.y, f3.y};
            #pragma unroll
            for (int j = 0; j < 4; j++) if (colb + j < N) {
                Cb[r0 + colb + j] = o0[j] + bsv[j];
                Cb[r1 + colb + j] = o1[j] + bsv[j];
            }
        }
    }
}

// ===========================================================================
// delta GEMM: delta = softplus(dt @ dtw^T + dtb); du = delta * xc
// ===========================================================================
__global__ __launch_bounds__(256) void delta_gemm(
    const float* __restrict__ dtw0, const float* __restrict__ dtb0,
    const float* __restrict__ dtw1, const float* __restrict__ dtb1)
{
    __shared__ float As[DR][64];
    __shared__ float Bs[DR][64];
    const int dir = blockIdx.z;
    const float* Ab  = &g_xdbl[dir][0][0][0];
    const float* xcb = &g_xc[dir][0][0][0];
    float* pdl = &g_delta[dir][0][0][0];
    float* pdu = &g_du[dir][0][0][0];
    const float* dtw = dir ? dtw1 : dtw0;
    const float* dtb = dir ? dtb1 : dtb0;
    const int row0 = blockIdx.y * 64;
    const int col0 = blockIdx.x * 64;
    const int tid = threadIdx.x;
    const int tx = tid & 15, ty = tid >> 4;

    for (int i = tid; i < 64 * DR; i += 256) {
        int r = i / DR, k = i % DR;
        As[k][r] = Ab[(long)(row0 + r) * XW + k];
        Bs[k][r] = dtw[(long)(col0 + r) * DR + k];
    }
    __syncthreads();

    unsigned long long acc[2][4];
    #pragma unroll
    for (int i = 0; i < 2; i++)
        #pragma unroll
        for (int j = 0; j < 4; j++) acc[i][j] = 0ull;

    #pragma unroll
    for (int k = 0; k < DR; k++) {
        unsigned long long a01 = *(const unsigned long long*)&As[k][ty*4];
        unsigned long long a23 = *(const unsigned long long*)&As[k][ty*4+2];
        float4 bv = *(const float4*)&Bs[k][tx*4];
        unsigned long long b0 = dup2(bv.x), b1 = dup2(bv.y), b2 = dup2(bv.z), b3 = dup2(bv.w);
        ffma2(acc[0][0], a01, b0); ffma2(acc[0][1], a01, b1);
        ffma2(acc[0][2], a01, b2); ffma2(acc[0][3], a01, b3);
        ffma2(acc[1][0], a23, b0); ffma2(acc[1][1], a23, b1);
        ffma2(acc[1][2], a23, b2); ffma2(acc[1][3], a23, b3);
    }
    const int colb = col0 + tx*4;
    float4 bias4 = *(const float4*)&dtb[colb];
    float bsv[4] = {bias4.x, bias4.y, bias4.z, bias4.w};
    float out[4][4];
    #pragma unroll
    for (int i = 0; i < 2; i++)
        #pragma unroll
        for (int j = 0; j < 4; j++) {
            float2 f = unpk2(acc[i][j]);
            out[2*i][j] = f.x; out[2*i+1][j] = f.y;
        }
    #pragma unroll
    for (int r = 0; r < 4; r++) {
        long row = row0 + ty*4 + r;
        float4 xc4 = *(const float4*)&xcb[row * DI + colb];
        float xcv[4] = {xc4.x, xc4.y, xc4.z, xc4.w};
        float dl[4], du[4];
        #pragma unroll
        for (int j = 0; j < 4; j++) {
            float s = out[r][j] + bsv[j];
            float sp = fmaxf(s, 0.f) + log1pf(__expf(-fabsf(s)));
            dl[j] = sp;
            du[j] = sp * xcv[j];
        }
        *(float4*)&pdl[row * DI + colb] = make_float4(dl[0], dl[1], dl[2], dl[3]);
        *(float4*)&pdu[row * DI + colb] = make_float4(du[0], du[1], du[2], du[3]);
    }
}

// ----------------------------- B/C repack -----------------------------
__global__ __launch_bounds__(256) void repack_kernel()
{
    int id = blockIdx.x * 256 + threadIdx.x;
    if (id >= 2 * NB * LL * 2 * DS) return;
    int n = id & 15;
    int which = (id >> 4) & 1;
    int t = (id >> 5) & (LL - 1);
    int b = (id >> 17) & 1;
    int dir = (id >> 18) & 1;
    float v = g_xdbl[dir][b][t][DR + which * DS + n];
    float* dst = which ? &g_Cc[dir][b][0][0][0] : &g_Bc[dir][b][0][0][0];
    dst[(t >> 2) * (DS*4) + n * 4 + (t & 3)] = v;
}

// ----------------------------- depthwise causal conv + silu -----------------------------
__global__ __launch_bounds__(256) void conv_silu_kernel(
    const float* __restrict__ cw0, const float* __restrict__ cb0,
    const float* __restrict__ cw1, const float* __restrict__ cb1)
{
    long id = (long)blockIdx.x * 256 + threadIdx.x;
    const long total = (long)2 * NB * LL * DI;
    if (id >= total) return;
    int d = (int)(id % DI); long r = id / DI;
    int t = (int)(r % LL); r /= LL;
    int b = (int)(r % NB); int dir = (int)(r / NB);
    const float* cw = dir ? cw1 : cw0;
    const float* cb = dir ? cb1 : cb0;
    const float* xi = &g_xz[dir][b][0][0];
    float acc = cb[d];
    #pragma unroll
    for (int i = 0; i < 4; i++) {
        int tt = t - 3 + i;
        if (tt >= 0) acc += cw[d*4 + i] * xi[(long)tt * (2*DI) + d];
    }
    g_xc[dir][b][t][d] = acc / (1.f + __expf(-acc));
}

// ----------------------------- selective scan: thread = (dir,b,d,n) -----------------------------
__global__ __launch_bounds__(256) void scan_kernel(
    const float* __restrict__ Al0, const float* __restrict__ Al1)
{
    const int gid = blockIdx.x * 256 + threadIdx.x;
    const int n  = gid & 15;
    const int cj = gid >> 4;
    const int dir = cj / (NB * DI);
    const int rem = cj % (NB * DI);
    const int b = rem / DI;
    const int d = rem % DI;
    const float* Al = dir ? Al1 : Al0;
    const float Acoef = -__expf(Al[d*DS + n]);
    const float*  pd = &g_delta[dir][b][0][0];
    const float*  pu = &g_du[dir][b][0][0];
    const float4* pB = (const float4*)&g_Bc[dir][b][0][0][0];
    const float4* pC = (const float4*)&g_Cc[dir][b][0][0][0];
    float* py = &g_y[dir][b][0][0];
    float h = 0.f;
    float4 Bv = __ldg(&pB[n]);
    float4 Cv = __ldg(&pC[n]);
    for (int t4 = 0; t4 < LL/4; t4++) {
        float4 Bn = make_float4(0.f,0.f,0.f,0.f), Cn = Bn;
        if (t4 + 1 < LL/4) {
            Bn = __ldg(&pB[(t4+1)*16 + n]);
            Cn = __ldg(&pC[(t4+1)*16 + n]);
        }
        float dl[4], uu[4];
        #pragma unroll
        for (int j = 0; j < 4; j++) {
            long o = (long)(t4*4 + j) * DI + d;
            dl[j] = __ldg(pd + o);
            uu[j] = __ldg(pu + o);
        }
        float dA[4];
        #pragma unroll
        for (int j = 0; j < 4; j++) dA[j] = __expf(dl[j] * Acoef);
        #pragma unroll
        for (int j = 0; j < 4; j++) {
            int t = t4*4 + j;
            float Bj = (j==0) ? Bv.x : (j==1) ? Bv.y : (j==2) ? Bv.z : Bv.w;
            float Cj = (j==0) ? Cv.x : (j==1) ? Cv.y : (j==2) ? Cv.z : Cv.w;
            h = fmaf(dA[j], h, uu[j] * Bj);
            float p = h * Cj;
            p += __shfl_xor_sync(0xffffffffu, p, 1);
            p += __shfl_xor_sync(0xffffffffu, p, 2);
            p += __shfl_xor_sync(0xffffffffu, p, 4);
            p += __shfl_xor_sync(0xffffffffu, p, 8);
            if (n == 0) py[(long)t*DI + d] = p;
        }
        Bv = Bn; Cv = Cn;
    }
}

// ----------------------------- gate: (y + xc*D) * silu(z) -> bf16 hi/lo -----------------------------
__global__ __launch_bounds__(256) void gate_kernel(
    const float* __restrict__ D0, const float* __restrict__ D1)
{
    long e = ((long)blockIdx.x * 256 + threadIdx.x) * 4;
    const long total = (long)2 * NB * LL * DI;
    if (e >= total) return;
    int d = (int)(e % DI); long r = e / DI;
    int t = (int)(r % LL); r /= LL;
    int b = (int)(r % NB); int dir = (int)(r / NB);
    float4 Dp = *(const float4*)&(dir ? D1 : D0)[d];
    float4 y4  = *(const float4*)&g_y[dir][b][t][d];
    float4 xc4 = *(const float4*)&g_xc[dir][b][t][d];
    float4 z4  = *(const float4*)&g_xz[dir][b][t][DI + d];
    float gv[4];
    float yv[4] = {y4.x + xc4.x*Dp.x, y4.y + xc4.y*Dp.y, y4.z + xc4.z*Dp.z, y4.w + xc4.w*Dp.w};
    float zv[4] = {z4.x, z4.y, z4.z, z4.w};
    #pragma unroll
    for (int j = 0; j < 4; j++)
        gv[j] = yv[j] * (zv[j] / (1.f + __expf(-zv[j])));
    uint32_t* Oh = (uint32_t*)&g_gate_hi[dir][b][t][d];
    uint32_t* Ol = (uint32_t*)&g_gate_lo[dir][b][t][d];
    float h0 = __bfloat162float(__float2bfloat16(gv[0]));
    float h1 = __bfloat162float(__float2bfloat16(gv[1]));
    float h2 = __bfloat162float(__float2bfloat16(gv[2]));
    float h3 = __bfloat162float(__float2bfloat16(gv[3]));
    Oh[0] = packbf(gv[0], gv[1]);
    Oh[1] = packbf(gv[2], gv[3]);
    Ol[0] = packbf(gv[0] - h0, gv[1] - h1);
    Ol[1] = packbf(gv[2] - h2, gv[3] - h3);
}

// ----------------------------- GLU + partial stats -----------------------------
__global__ __launch_bounds__(256) void glu_kernel()
{
    const int batch = blockIdx.y;
    const int tid = threadIdx.x;
    float lsum = 0.f, lssq = 0.f;
    const float* yc = &g_yc[batch][0][0];
    float* gl = &g_glu[batch][0][0];
    for (int it = 0; it < 128; it++) {
        long e = (long)blockIdx.x * 32768 + (long)it * 256 + tid;
        int t = (int)(e / DM), o = (int)(e % DM);
        float a  = yc[(long)t * (2*DM) + o];
        float bg = yc[(long)t * (2*DM) + DM + o];
        float g = a * (1.f / (1.f + __expf(-bg)));
        gl[e] = g;
        lsum += g; lssq += g * g;
    }
    __shared__ float s1[256], s2[256];
    s1[tid] = lsum; s2[tid] = lssq;
    __syncthreads();
    for (int s = 128; s > 0; s >>= 1) {
        if (tid < s) { s1[tid] += s1[tid+s]; s2[tid] += s2[tid+s]; }
        __syncthreads();
    }
    if (tid == 0) g_part[batch][blockIdx.x] = make_float2(s1[0], s2[0]);
}

__global__ void stats_kernel()
{
    int b = threadIdx.x;
    if (b < NB) {
        float sum = 0.f, ssq = 0.f;
        for (int i = 0; i < 48; i++) { float2 p = g_part[b][i]; sum += p.x; ssq += p.y; }
        const float inv = 1.f / ((float)DM * (float)LL);
        float mu = sum * inv;
        float var = ssq * inv - mu * mu;
        g_stats[b] = make_float2(mu, rsqrtf(var + 1e-5f));
    }
}

// ----------------------------- normalize + transpose to output [b][c][t] -----------------------------
__global__ __launch_bounds__(256) void norm_kernel(
    const float* __restrict__ gnw, const float* __restrict__ gnb,
    float* __restrict__ out)
{
    __shared__ float s[32][33];
    const int b = blockIdx.z;
    const int t0 = blockIdx.x * 32;
    const int c0 = blockIdx.y * 32;
    const int tx = threadIdx.x & 31;
    const int ty = threadIdx.x >> 5;
    #pragma unroll
    for (int j = 0; j < 4; j++) {
        int t = t0 + ty + j*8;
        s[ty + j*8][tx] = g_glu[b][t][c0 + tx];
    }
    __syncthreads();
    float2 st = g_stats[b];
    #pragma unroll
    for (int j = 0; j < 4; j++) {
        int c = c0 + ty + j*8;
        float v = s[tx][ty + j*8];
        out[((long)b * DM + c) * LL + t0 + tx] = (v - st.x) * st.y * gnw[c] + gnb[c];
    }
}

// ----------------------------- launch -----------------------------
extern "C" void kernel_launch(void* const* d_in, const int* in_sizes, int n_in,
                              void* d_out, int out_size)
{
    (void)in_sizes; (void)n_in; (void)out_size;
    const float* x        = (const float*)d_in[0];
    const float* f_in_w   = (const float*)d_in[1];
    const float* f_conv_w = (const float*)d_in[2];
    const float* f_conv_b = (const float*)d_in[3];
    const float* f_xproj  = (const float*)d_in[4];
    const float* f_dt_w   = (const float*)d_in[5];
    const float* f_dt_b   = (const float*)d_in[6];
    const float* f_A_log  = (const float*)d_in[7];
    const float* f_D      = (const float*)d_in[8];
    const float* f_out_w  = (const float*)d_in[9];
    const float* b_in_w   = (const float*)d_in[10];
    const float* b_conv_w = (const float*)d_in[11];
    const float* b_conv_b = (const float*)d_in[12];
    const float* b_xproj  = (const float*)d_in[13];
    const float* b_dt_w   = (const float*)d_in[14];
    const float* b_dt_b   = (const float*)d_in[15];
    const float* b_A_log  = (const float*)d_in[16];
    const float* b_D      = (const float*)d_in[17];
    const float* b_out_w  = (const float*)d_in[18];
    const float* c_w      = (const float*)d_in[19];
    const float* c_b      = (const float*)d_in[20];
    const float* gn_w     = (const float*)d_in[21];
    const float* gn_b     = (const float*)d_in[22];
    float* out = (float*)d_out;

    float *pxz, *pxc, *pxdbl, *pyc;
    cudaGetSymbolAddress((void**)&pxz,   g_xz);
    cudaGetSymbolAddress((void**)&pxc,   g_xc);
    cudaGetSymbolAddress((void**)&pxdbl, g_xdbl);
    cudaGetSymbolAddress((void**)&pyc,   g_yc);
    __nv_bfloat16 *pxT_hi, *pxT_lo, *pinw_hi, *pinw_lo, *pgate_hi, *pgate_lo;
    __nv_bfloat16 *poutw_hi, *poutw_lo, *pycat_hi, *pycat_lo, *pcw_hi, *pcw_lo;
    cudaGetSymbolAddress((void**)&pxT_hi,   g_xT_hi);
    cudaGetSymbolAddress((void**)&pxT_lo,   g_xT_lo);
    cudaGetSymbolAddress((void**)&pinw_hi,  g_inw_hi);
    cudaGetSymbolAddress((void**)&pinw_lo,  g_inw_lo);
    cudaGetSymbolAddress((void**)&pgate_hi, g_gate_hi);
    cudaGetSymbolAddress((void**)&pgate_lo, g_gate_lo);
    cudaGetSymbolAddress((void**)&poutw_hi, g_outw_hi);
    cudaGetSymbolAddress((void**)&poutw_lo, g_outw_lo);
    cudaGetSymbolAddress((void**)&pycat_hi, g_ycat_hi);
    cudaGetSymbolAddress((void**)&pycat_lo, g_ycat_lo);
    cudaGetSymbolAddress((void**)&pcw_hi,   g_cw_hi);
    cudaGetSymbolAddress((void**)&pcw_lo,   g_cw_lo);

    static bool attr_set = false;
    if (!attr_set) {
        cudaFuncSetAttribute(hmma_gemm, cudaFuncAttributeMaxDynamicSharedMemorySize, HMMA_SMEM);
        attr_set = true;
    }

    const long INW = (long)(2*DI) * DM;   // 589824
    const long OUTW = (long)DM * DI;      // 294912
    const long CWN = (long)(2*DM) * (2*DM);

    // 0) transpose x -> bf16 hi/lo ; convert weights
    transpose_x<<<dim3(LL/32, DM/32, NB), 256>>>(x);
    convert_pair<<<(unsigned)((INW/2 + 255)/256), 256>>>(f_in_w, pinw_hi, pinw_lo, (int)(INW/2));
    convert_pair<<<(unsigned)((INW/2 + 255)/256), 256>>>(b_in_w, pinw_hi + INW, pinw_lo + INW, (int)(INW/2));
    convert_pair<<<(unsigned)((OUTW/2 + 255)/256), 256>>>(f_out_w, poutw_hi, poutw_lo, (int)(OUTW/2));
    convert_pair<<<(unsigned)((OUTW/2 + 255)/256), 256>>>(b_out_w, poutw_hi + OUTW, poutw_lo + OUTW, (int)(OUTW/2));
    convert_pair<<<(unsigned)((CWN/2 + 255)/256), 256>>>(c_w, pcw_hi, pcw_lo, (int)(CWN/2));

    // 1) in-projection (HMMA): z=dir*2+b, M=4096, N=1536, K=384 -> fp32 g_xz
    hmma_gemm<<<dim3(24, 32, 4), 256, HMMA_SMEM>>>(
        pxT_hi, pxT_lo, DM, (long)LL*DM,
        pinw_hi, pinw_lo, pinw_hi + INW, pinw_lo + INW,
        nullptr,
        pxz, nullptr, nullptr,
        2*DI, (long)LL*2*DI, DM, 0);

    // 2) depthwise causal conv + silu
    {
        long total = (long)2 * NB * LL * DI;
        conv_silu_kernel<<<(unsigned)((total + 255) / 256), 256>>>(f_conv_w, f_conv_b, b_conv_w, b_conv_b);
    }

    // 3) x-projection -> xdbl (N=56, f32x2 path)
    gemm128<<<dim3(1, (NB*LL)/128, 2), 256>>>(
        pxc, DI, (long)NB*LL*DI,
        f_xproj, b_xproj, nullptr,
        pxdbl, XW, (long)NB*LL*XW,
        XW, DI);

    // 4) delta + du; 4b) repack; 5) scan
    delta_gemm<<<dim3(DI/64, (NB*LL)/64, 2), 256>>>(f_dt_w, f_dt_b, b_dt_w, b_dt_b);
    repack_kernel<<<2048, 256>>>();
    scan_kernel<<<192, 256>>>(f_A_log, b_A_log);

    // 6) gate -> bf16 hi/lo
    {
        long total = (long)2 * NB * LL * DI / 4;
        gate_kernel<<<(unsigned)((total + 255) / 256), 256>>>(f_D, b_D);
    }

    // 7) out-projection (HMMA): z=dir, M=8192, N=384, K=768 -> bf16 ycat col halves
    hmma_gemm<<<dim3(6, 64, 2), 256, HMMA_SMEM>>>(
        pgate_hi, pgate_lo, DI, (long)NB*LL*DI,
        poutw_hi, poutw_lo, poutw_hi + OUTW, poutw_lo + OUTW,
        nullptr,
        nullptr, pycat_hi, pycat_lo,
        2*DM, (long)DM, DI, 1);

    // 8) final 1x1 conv (HMMA): M=8192, N=768, K=768, bias -> fp32 g_yc
    hmma_gemm<<<dim3(12, 64, 1), 256, HMMA_SMEM>>>(
        pycat_hi, pycat_lo, 2*DM, 0L,
        pcw_hi, pcw_lo, pcw_hi, pcw_lo,
        c_b,
        pyc, nullptr, nullptr,
        2*DM, 0L, 2*DM, 2);

    // 9) GLU + partial stats; 10) stats; 11) normalize + transpose out
    glu_kernel<<<dim3(48, 2), 256>>>();
    stats_kernel<<<1, 32>>>();
    norm_kernel<<<dim3(LL/32, DM/32, NB), 256>>>(gn_w, gn_b, out);
}

// round 9
// speedup vs baseline: 1.7593x; 1.1034x over previous
#include <cuda_runtime.h>
#include <cuda_fp16.h>
#include <cstdint>

#define LL 4096
#define DM 384
#define DI 768
#define DS 16
#define DR 24
#define NB 2
#define XW (DR + 2*DS)   // 56

// ----------------------------- scratch (device globals) -----------------------------
__device__ float g_xz   [2][NB][LL][2*DI];   // in-proj output
__device__ float g_xc   [2][NB][LL][DI];     // after causal conv + silu (fp32)
__device__ float g_xdbl [2][NB][LL][XW];     // x-proj output (dt | B | C)
__device__ float g_delta[2][NB][LL][DI];
__device__ float g_du   [2][NB][LL][DI];
__device__ float g_Bc   [2][NB][LL/4][DS][4];
__device__ float g_Cc   [2][NB][LL/4][DS][4];
__device__ float g_y    [2][NB][LL][DI];
__device__ float g_yc   [NB][LL][2*DM];
__device__ float g_glu  [NB][LL][DM];
__device__ float2 g_part[NB][64];
__device__ float2 g_stats[NB];

// fp16 operand buffers for HMMA GEMMs
__device__ __align__(16) __half g_xT16  [NB][LL][DM];
__device__ __align__(16) __half g_inw16 [2][2*DI][DM];
__device__ __align__(16) __half g_xch16 [2][NB][LL][DI];
__device__ __align__(16) __half g_xpw16 [2][64][DI];      // xproj W padded 56->64
__device__ __align__(16) __half g_gate16[2][NB][LL][DI];
__device__ __align__(16) __half g_outw16[2][DM][DI];
__device__ __align__(16) __half g_ycat16[NB][LL][2*DM];
__device__ __align__(16) __half g_cw16  [2*DM][2*DM];

// ----------------------------- helpers -----------------------------
__device__ __forceinline__ uint32_t smem_to_u32(const void* p) {
    uint32_t a;
    asm("{ .reg .u64 t; cvta.to.shared.u64 t, %1; cvt.u32.u64 %0, t; }" : "=r"(a) : "l"(p));
    return a;
}
__device__ __forceinline__ void ldsm4(uint32_t* r, uint32_t addr){
    asm volatile("ldmatrix.sync.aligned.m8n8.x4.shared.b16 {%0,%1,%2,%3}, [%4];"
        : "=r"(r[0]), "=r"(r[1]), "=r"(r[2]), "=r"(r[3]) : "r"(addr));
}
__device__ __forceinline__ void mma_f16(float* c, const uint32_t* a, const uint32_t* b){
    asm volatile("mma.sync.aligned.m16n8k16.row.col.f32.f16.f16.f32 "
        "{%0,%1,%2,%3}, {%4,%5,%6,%7}, {%8,%9}, {%0,%1,%2,%3};"
        : "+f"(c[0]), "+f"(c[1]), "+f"(c[2]), "+f"(c[3])
        : "r"(a[0]), "r"(a[1]), "r"(a[2]), "r"(a[3]), "r"(b[0]), "r"(b[1]));
}
__device__ __forceinline__ void cpasync16(uint32_t s, const void* g){
    asm volatile("cp.async.cg.shared.global [%0], [%1], 16;" :: "r"(s), "l"(g));
}
#define CP_COMMIT() asm volatile("cp.async.commit_group;" ::: "memory")
template<int N> __device__ __forceinline__ void cpwait(){
    asm volatile("cp.async.wait_group %0;" :: "n"(N) : "memory");
}

// ===========================================================================
// fp16 HMMA GEMM: tile 128x64, K-chunk 64, 4-stage cp.async pipeline.
// A fp16 row-major [.][lda] (+row reversal for mode 0 bwd), W fp16 [N][K].
// mode 0 (inproj): z=dir*2+b -> A+(z&1)*Az, rev=z>>1, W=(z>>1)?W1:W0
// mode 1 (other) : A+z*Az, rev=0, W=z?W1:W0
// Output: Ch!=null -> fp16 out; else fp32 (+optional bias). Col-guard ncols.
// ===========================================================================
#define SMF_W 16384u
#define SMF_STAGE 24576u
#define HMMA16_SMEM (4 * SMF_STAGE)   // 98304

__device__ __forceinline__ void load_chunk16(
    uint32_t bufb, const __half* __restrict__ A, const __half* __restrict__ W,
    int lda, int ldw, int k0, int row0, int col0, int rev, int tid)
{
    #pragma unroll
    for (int i = 0; i < 4; i++) {
        int u = i * 256 + tid;            // 0..1023 -> A 128 rows x 4 x 16B
        int rr = u >> 3, c8 = u & 7;
        int ar = rev ? (LL - 1 - (row0 + rr)) : (row0 + rr);
        uint32_t off = ((uint32_t)(rr * 128 + c8 * 16)) ^ ((uint32_t)(rr & 7) << 4);
        cpasync16(bufb + off, A + (long)ar * lda + k0 + c8 * 8);
    }
    #pragma unroll
    for (int i = 0; i < 2; i++) {
        int u = i * 256 + tid;            // 0..511 -> W 64 rows
        int rr = u >> 3, c8 = u & 7;
        uint32_t off = ((uint32_t)(rr * 128 + c8 * 16)) ^ ((uint32_t)(rr & 7) << 4);
        cpasync16(bufb + SMF_W + off, W + (long)(col0 + rr) * ldw + k0 + c8 * 8);
    }
}

__global__ __launch_bounds__(256, 2) void hmma16(
    const __half* __restrict__ A, int lda, long Az,
    const __half* __restrict__ W0, const __half* __restrict__ W1,
    const float* __restrict__ bias,
    float* __restrict__ Cf, __half* __restrict__ Ch,
    int ldc, long Cz, int K, int ncols, int mode)
{
    extern __shared__ __align__(16) char sm[];
    const uint32_t sb = smem_to_u32(sm);

    const int tid  = threadIdx.x;
    const int lane = tid & 31;
    const int warp = tid >> 5;
    const int m0w = (warp >> 1) * 32;
    const int n0w = (warp & 1) * 32;

    const int z = blockIdx.z;
    const int row0 = blockIdx.y * 128;
    const int col0 = blockIdx.x * 64;

    const __half *pA, *pW;
    int rev = 0;
    if (mode == 0) {
        pA = A + (long)(z & 1) * Az;
        rev = z >> 1;
        pW = (z >> 1) ? W1 : W0;
    } else {
        pA = A + (long)z * Az;
        pW = z ? W1 : W0;
    }

    float acc[2][4][4];
    #pragma unroll
    for (int i = 0; i < 2; i++)
        #pragma unroll
        for (int j = 0; j < 4; j++)
            #pragma unroll
            for (int q = 0; q < 4; q++) acc[i][j][q] = 0.f;

    const int lj = lane >> 3;
    const int lr = lane & 7;
    const int nc = K >> 6;

    load_chunk16(sb,             pA, pW, lda, K, 0,  row0, col0, rev, tid); CP_COMMIT();
    load_chunk16(sb + SMF_STAGE, pA, pW, lda, K, 64, row0, col0, rev, tid); CP_COMMIT();

    for (int c = 0; c < nc; c++) {
        if (c + 2 < nc) {
            load_chunk16(sb + ((c + 2) & 3) * SMF_STAGE, pA, pW, lda, K,
                         (c + 2) << 6, row0, col0, rev, tid);
            CP_COMMIT();
            cpwait<2>();
        } else if (c + 1 < nc) {
            cpwait<1>();
        } else {
            cpwait<0>();
        }
        __syncthreads();
        const uint32_t bufb = sb + (c & 3) * SMF_STAGE;
        #pragma unroll
        for (int ks = 0; ks < 4; ks++) {
            const int kb = ks * 16;
            uint32_t af[2][4], bf[2][4];
            #pragma unroll
            for (int mh = 0; mh < 2; mh++) {
                int row = m0w + mh * 16 + ((lj & 1) << 3) + lr;
                int kc  = kb + ((lj >> 1) << 3);
                uint32_t off = ((uint32_t)(row * 128 + kc * 2)) ^ ((uint32_t)(row & 7) << 4);
                ldsm4(af[mh], bufb + off);
            }
            #pragma unroll
            for (int np = 0; np < 2; np++) {
                int row = n0w + np * 16 + ((lj >> 1) << 3) + lr;
                int kc  = kb + ((lj & 1) << 3);
                uint32_t off = ((uint32_t)(row * 128 + kc * 2)) ^ ((uint32_t)(row & 7) << 4);
                ldsm4(bf[np], bufb + SMF_W + off);
            }
            #pragma unroll
            for (int mh = 0; mh < 2; mh++) {
                #pragma unroll
                for (int ng = 0; ng < 4; ng++)
                    mma_f16(acc[mh][ng], af[mh], &bf[ng >> 1][(ng & 1) * 2]);
            }
        }
    }

    // ---- epilogue ----
    const int g = lane >> 2, tig = lane & 3;
    if (Ch) {
        __half* Cb = Ch + (long)z * Cz;
        #pragma unroll
        for (int mh = 0; mh < 2; mh++) {
            #pragma unroll
            for (int ng = 0; ng < 4; ng++) {
                int row = row0 + m0w + mh * 16 + g;
                int col = col0 + n0w + ng * 8 + tig * 2;
                if (col < ncols) {
                    *(__half2*)&Cb[(long)row * ldc + col] =
                        __floats2half2_rn(acc[mh][ng][0], acc[mh][ng][1]);
                    *(__half2*)&Cb[(long)(row + 8) * ldc + col] =
                        __floats2half2_rn(acc[mh][ng][2], acc[mh][ng][3]);
                }
            }
        }
    } else {
        float* Cb = Cf + (long)z * Cz;
        #pragma unroll
        for (int mh = 0; mh < 2; mh++) {
            #pragma unroll
            for (int ng = 0; ng < 4; ng++) {
                int row = row0 + m0w + mh * 16 + g;
                int col = col0 + n0w + ng * 8 + tig * 2;
                if (col < ncols) {
                    float b0 = 0.f, b1 = 0.f;
                    if (bias) { b0 = bias[col]; b1 = bias[col + 1]; }
                    *(float2*)&Cb[(long)row * ldc + col] =
                        make_float2(acc[mh][ng][0] + b0, acc[mh][ng][1] + b1);
                    *(float2*)&Cb[(long)(row + 8) * ldc + col] =
                        make_float2(acc[mh][ng][2] + b0, acc[mh][ng][3] + b1);
                }
            }
        }
    }
}

// ----------------------------- fp32 -> fp16 convert (pairs) -----------------------------
__global__ __launch_bounds__(256) void convert16(
    const float* __restrict__ src, __half* __restrict__ dst, int npairs)
{
    int i = blockIdx.x * 256 + threadIdx.x;
    if (i >= npairs) return;
    float2 v = *(const float2*)&src[i * 2];
    ((__half2*)dst)[i] = __floats2half2_rn(v.x, v.y);
}

// ----------------------------- xproj weights: pad 56 -> 64 rows, fp16 -----------------------------
__global__ __launch_bounds__(256) void pad_xprojw(
    const float* __restrict__ w0, const float* __restrict__ w1)
{
    int i = blockIdx.x * 256 + threadIdx.x;   // over 2*64*DI
    if (i >= 2 * 64 * DI) return;
    int k = i % DI;
    int r = (i / DI) & 63;
    int dir = i / (64 * DI);
    const float* w = dir ? w1 : w0;
    float v = (r < XW) ? w[r * DI + k] : 0.f;
    g_xpw16[dir][r][k] = __float2half(v);
}

// ----------------------------- x transpose: [b][c][t] -> fp16 [b][t][c] -----------------------------
__global__ __launch_bounds__(256) void transpose_x(const float* __restrict__ x)
{
    __shared__ float s[32][33];
    const int b = blockIdx.z;
    const int t0 = blockIdx.x * 32;
    const int c0 = blockIdx.y * 32;
    const int tx = threadIdx.x & 31;
    const int ty = threadIdx.x >> 5;
    #pragma unroll
    for (int j = 0; j < 4; j++)
        s[ty + j*8][tx] = x[((long)b * DM + c0 + ty + j*8) * LL + t0 + tx];
    __syncthreads();
    #pragma unroll
    for (int j = 0; j < 4; j++)
        g_xT16[b][t0 + ty + j*8][c0 + tx] = __float2half(s[tx][ty + j*8]);
}

// ----------------------------- f32x2 helpers (delta_gemm) -----------------------------
__device__ __forceinline__ unsigned long long dup2(float x){
    unsigned long long r; asm("mov.b64 %0, {%1, %1};" : "=l"(r) : "f"(x)); return r;
}
__device__ __forceinline__ void ffma2(unsigned long long &d, unsigned long long a, unsigned long long b){
    asm("fma.rn.f32x2 %0, %1, %2, %0;" : "+l"(d) : "l"(a), "l"(b));
}
__device__ __forceinline__ float2 unpk2(unsigned long long v){
    float2 f; asm("mov.b64 {%0, %1}, %2;" : "=f"(f.x), "=f"(f.y) : "l"(v)); return f;
}

// ===========================================================================
// delta GEMM: delta = softplus(dt @ dtw^T + dtb); du = delta * xc
// ===========================================================================
__global__ __launch_bounds__(256) void delta_gemm(
    const float* __restrict__ dtw0, const float* __restrict__ dtb0,
    const float* __restrict__ dtw1, const float* __restrict__ dtb1)
{
    __shared__ float As[DR][64];
    __shared__ float Bs[DR][64];
    const int dir = blockIdx.z;
    const float* Ab  = &g_xdbl[dir][0][0][0];
    const float* xcb = &g_xc[dir][0][0][0];
    float* pdl = &g_delta[dir][0][0][0];
    float* pdu = &g_du[dir][0][0][0];
    const float* dtw = dir ? dtw1 : dtw0;
    const float* dtb = dir ? dtb1 : dtb0;
    const int row0 = blockIdx.y * 64;
    const int col0 = blockIdx.x * 64;
    const int tid = threadIdx.x;
    const int tx = tid & 15, ty = tid >> 4;

    for (int i = tid; i < 64 * DR; i += 256) {
        int r = i / DR, k = i % DR;
        As[k][r] = Ab[(long)(row0 + r) * XW + k];
        Bs[k][r] = dtw[(long)(col0 + r) * DR + k];
    }
    __syncthreads();

    unsigned long long acc[2][4];
    #pragma unroll
    for (int i = 0; i < 2; i++)
        #pragma unroll
        for (int j = 0; j < 4; j++) acc[i][j] = 0ull;

    #pragma unroll
    for (int k = 0; k < DR; k++) {
        unsigned long long a01 = *(const unsigned long long*)&As[k][ty*4];
        unsigned long long a23 = *(const unsigned long long*)&As[k][ty*4+2];
        float4 bv = *(const float4*)&Bs[k][tx*4];
        unsigned long long b0 = dup2(bv.x), b1 = dup2(bv.y), b2 = dup2(bv.z), b3 = dup2(bv.w);
        ffma2(acc[0][0], a01, b0); ffma2(acc[0][1], a01, b1);
        ffma2(acc[0][2], a01, b2); ffma2(acc[0][3], a01, b3);
        ffma2(acc[1][0], a23, b0); ffma2(acc[1][1], a23, b1);
        ffma2(acc[1][2], a23, b2); ffma2(acc[1][3], a23, b3);
    }
    const int colb = col0 + tx*4;
    float4 bias4 = *(const float4*)&dtb[colb];
    float bsv[4] = {bias4.x, bias4.y, bias4.z, bias4.w};
    float out[4][4];
    #pragma unroll
    for (int i = 0; i < 2; i++)
        #pragma unroll
        for (int j = 0; j < 4; j++) {
            float2 f = unpk2(acc[i][j]);
            out[2*i][j] = f.x; out[2*i+1][j] = f.y;
        }
    #pragma unroll
    for (int r = 0; r < 4; r++) {
        long row = row0 + ty*4 + r;
        float4 xc4 = *(const float4*)&xcb[row * DI + colb];
        float xcv[4] = {xc4.x, xc4.y, xc4.z, xc4.w};
        float dl[4], du[4];
        #pragma unroll
        for (int j = 0; j < 4; j++) {
            float s = out[r][j] + bsv[j];
            float sp = fmaxf(s, 0.f) + log1pf(__expf(-fabsf(s)));
            dl[j] = sp;
            du[j] = sp * xcv[j];
        }
        *(float4*)&pdl[row * DI + colb] = make_float4(dl[0], dl[1], dl[2], dl[3]);
        *(float4*)&pdu[row * DI + colb] = make_float4(du[0], du[1], du[2], du[3]);
    }
}

// ----------------------------- B/C repack -----------------------------
__global__ __launch_bounds__(256) void repack_kernel()
{
    int id = blockIdx.x * 256 + threadIdx.x;
    if (id >= 2 * NB * LL * 2 * DS) return;
    int n = id & 15;
    int which = (id >> 4) & 1;
    int t = (id >> 5) & (LL - 1);
    int b = (id >> 17) & 1;
    int dir = (id >> 18) & 1;
    float v = g_xdbl[dir][b][t][DR + which * DS + n];
    float* dst = which ? &g_Cc[dir][b][0][0][0] : &g_Bc[dir][b][0][0][0];
    dst[(t >> 2) * (DS*4) + n * 4 + (t & 3)] = v;
}

// ----------------------------- depthwise causal conv + silu (fp32 + fp16 out) -----------------------------
__global__ __launch_bounds__(256) void conv_silu_kernel(
    const float* __restrict__ cw0, const float* __restrict__ cb0,
    const float* __restrict__ cw1, const float* __restrict__ cb1)
{
    long id = (long)blockIdx.x * 256 + threadIdx.x;
    const long total = (long)2 * NB * LL * DI;
    if (id >= total) return;
    int d = (int)(id % DI); long r = id / DI;
    int t = (int)(r % LL); r /= LL;
    int b = (int)(r % NB); int dir = (int)(r / NB);
    const float* cw = dir ? cw1 : cw0;
    const float* cb = dir ? cb1 : cb0;
    const float* xi = &g_xz[dir][b][0][0];
    float acc = cb[d];
    #pragma unroll
    for (int i = 0; i < 4; i++) {
        int tt = t - 3 + i;
        if (tt >= 0) acc += cw[d*4 + i] * xi[(long)tt * (2*DI) + d];
    }
    float v = acc / (1.f + __expf(-acc));
    g_xc[dir][b][t][d] = v;
    g_xch16[dir][b][t][d] = __float2half(v);
}

// ----------------------------- selective scan: thread = (dir,b,d,n) -----------------------------
__global__ __launch_bounds__(256) void scan_kernel(
    const float* __restrict__ Al0, const float* __restrict__ Al1)
{
    const int gid = blockIdx.x * 256 + threadIdx.x;
    const int n  = gid & 15;
    const int cj = gid >> 4;
    const int dir = cj / (NB * DI);
    const int rem = cj % (NB * DI);
    const int b = rem / DI;
    const int d = rem % DI;
    const float* Al = dir ? Al1 : Al0;
    const float Acoef = -__expf(Al[d*DS + n]);
    const float*  pd = &g_delta[dir][b][0][0];
    const float*  pu = &g_du[dir][b][0][0];
    const float4* pB = (const float4*)&g_Bc[dir][b][0][0][0];
    const float4* pC = (const float4*)&g_Cc[dir][b][0][0][0];
    float* py = &g_y[dir][b][0][0];
    float h = 0.f;
    float4 Bv = __ldg(&pB[n]);
    float4 Cv = __ldg(&pC[n]);
    for (int t4 = 0; t4 < LL/4; t4++) {
        float4 Bn = make_float4(0.f,0.f,0.f,0.f), Cn = Bn;
        if (t4 + 1 < LL/4) {
            Bn = __ldg(&pB[(t4+1)*16 + n]);
            Cn = __ldg(&pC[(t4+1)*16 + n]);
        }
        float dl[4], uu[4];
        #pragma unroll
        for (int j = 0; j < 4; j++) {
            long o = (long)(t4*4 + j) * DI + d;
            dl[j] = __ldg(pd + o);
            uu[j] = __ldg(pu + o);
        }
        float dA[4];
        #pragma unroll
        for (int j = 0; j < 4; j++) dA[j] = __expf(dl[j] * Acoef);
        #pragma unroll
        for (int j = 0; j < 4; j++) {
            int t = t4*4 + j;
            float Bj = (j==0) ? Bv.x : (j==1) ? Bv.y : (j==2) ? Bv.z : Bv.w;
            float Cj = (j==0) ? Cv.x : (j==1) ? Cv.y : (j==2) ? Cv.z : Cv.w;
            h = fmaf(dA[j], h, uu[j] * Bj);
            float p = h * Cj;
            p += __shfl_xor_sync(0xffffffffu, p, 1);
            p += __shfl_xor_sync(0xffffffffu, p, 2);
            p += __shfl_xor_sync(0xffffffffu, p, 4);
            p += __shfl_xor_sync(0xffffffffu, p, 8);
            if (n == 0) py[(long)t*DI + d] = p;
        }
        Bv = Bn; Cv = Cn;
    }
}

// ----------------------------- gate: (y + xc*D) * silu(z) -> fp16 -----------------------------
__global__ __launch_bounds__(256) void gate_kernel(
    const float* __restrict__ D0, const float* __restrict__ D1)
{
    long e = ((long)blockIdx.x * 256 + threadIdx.x) * 4;
    const long total = (long)2 * NB * LL * DI;
    if (e >= total) return;
    int d = (int)(e % DI); long r = e / DI;
    int t = (int)(r % LL); r /= LL;
    int b = (int)(r % NB); int dir = (int)(r / NB);
    float4 Dp = *(const float4*)&(dir ? D1 : D0)[d];
    float4 y4  = *(const float4*)&g_y[dir][b][t][d];
    float4 xc4 = *(const float4*)&g_xc[dir][b][t][d];
    float4 z4  = *(const float4*)&g_xz[dir][b][t][DI + d];
    float yv[4] = {y4.x + xc4.x*Dp.x, y4.y + xc4.y*Dp.y, y4.z + xc4.z*Dp.z, y4.w + xc4.w*Dp.w};
    float zv[4] = {z4.x, z4.y, z4.z, z4.w};
    float gv[4];
    #pragma unroll
    for (int j = 0; j < 4; j++)
        gv[j] = yv[j] * (zv[j] / (1.f + __expf(-zv[j])));
    __half2* Oh = (__half2*)&g_gate16[dir][b][t][d];
    Oh[0] = __floats2half2_rn(gv[0], gv[1]);
    Oh[1] = __floats2half2_rn(gv[2], gv[3]);
}

// ----------------------------- GLU + partial stats -----------------------------
__global__ __launch_bounds__(256) void glu_kernel()
{
    const int batch = blockIdx.y;
    const int tid = threadIdx.x;
    float lsum = 0.f, lssq = 0.f;
    const float* yc = &g_yc[batch][0][0];
    float* gl = &g_glu[batch][0][0];
    for (int it = 0; it < 128; it++) {
        long e = (long)blockIdx.x * 32768 + (long)it * 256 + tid;
        int t = (int)(e / DM), o = (int)(e % DM);
        float a  = yc[(long)t * (2*DM) + o];
        float bg = yc[(long)t * (2*DM) + DM + o];
        float g = a * (1.f / (1.f + __expf(-bg)));
        gl[e] = g;
        lsum += g; lssq += g * g;
    }
    __shared__ float s1[256], s2[256];
    s1[tid] = lsum; s2[tid] = lssq;
    __syncthreads();
    for (int s = 128; s > 0; s >>= 1) {
        if (tid < s) { s1[tid] += s1[tid+s]; s2[tid] += s2[tid+s]; }
        __syncthreads();
    }
    if (tid == 0) g_part[batch][blockIdx.x] = make_float2(s1[0], s2[0]);
}

__global__ void stats_kernel()
{
    int b = threadIdx.x;
    if (b < NB) {
        float sum = 0.f, ssq = 0.f;
        for (int i = 0; i < 48; i++) { float2 p = g_part[b][i]; sum += p.x; ssq += p.y; }
        const float inv = 1.f / ((float)DM * (float)LL);
        float mu = sum * inv;
        float var = ssq * inv - mu * mu;
        g_stats[b] = make_float2(mu, rsqrtf(var + 1e-5f));
    }
}

// ----------------------------- normalize + transpose to output [b][c][t] -----------------------------
__global__ __launch_bounds__(256) void norm_kernel(
    const float* __restrict__ gnw, const float* __restrict__ gnb,
    float* __restrict__ out)
{
    __shared__ float s[32][33];
    const int b = blockIdx.z;
    const int t0 = blockIdx.x * 32;
    const int c0 = blockIdx.y * 32;
    const int tx = threadIdx.x & 31;
    const int ty = threadIdx.x >> 5;
    #pragma unroll
    for (int j = 0; j < 4; j++) {
        int t = t0 + ty + j*8;
        s[ty + j*8][tx] = g_glu[b][t][c0 + tx];
    }
    __syncthreads();
    float2 st = g_stats[b];
    #pragma unroll
    for (int j = 0; j < 4; j++) {
        int c = c0 + ty + j*8;
        float v = s[tx][ty + j*8];
        out[((long)b * DM + c) * LL + t0 + tx] = (v - st.x) * st.y * gnw[c] + gnb[c];
    }
}

// ----------------------------- launch -----------------------------
extern "C" void kernel_launch(void* const* d_in, const int* in_sizes, int n_in,
                              void* d_out, int out_size)
{
    (void)in_sizes; (void)n_in; (void)out_size;
    const float* x        = (const float*)d_in[0];
    const float* f_in_w   = (const float*)d_in[1];
    const float* f_conv_w = (const float*)d_in[2];
    const float* f_conv_b = (const float*)d_in[3];
    const float* f_xproj  = (const float*)d_in[4];
    const float* f_dt_w   = (const float*)d_in[5];
    const float* f_dt_b   = (const float*)d_in[6];
    const float* f_A_log  = (const float*)d_in[7];
    const float* f_D      = (const float*)d_in[8];
    const float* f_out_w  = (const float*)d_in[9];
    const float* b_in_w   = (const float*)d_in[10];
    const float* b_conv_w = (const float*)d_in[11];
    const float* b_conv_b = (const float*)d_in[12];
    const float* b_xproj  = (const float*)d_in[13];
    const float* b_dt_w   = (const float*)d_in[14];
    const float* b_dt_b   = (const float*)d_in[15];
    const float* b_A_log  = (const float*)d_in[16];
    const float* b_D      = (const float*)d_in[17];
    const float* b_out_w  = (const float*)d_in[18];
    const float* c_w      = (const float*)d_in[19];
    const float* c_b      = (const float*)d_in[20];
    const float* gn_w     = (const float*)d_in[21];
    const float* gn_b     = (const float*)d_in[22];
    float* out = (float*)d_out;

    float *pxz, *pxdbl, *pyc;
    cudaGetSymbolAddress((void**)&pxz,   g_xz);
    cudaGetSymbolAddress((void**)&pxdbl, g_xdbl);
    cudaGetSymbolAddress((void**)&pyc,   g_yc);
    __half *pxT16, *pinw16, *pxch16, *pxpw16, *pgate16, *poutw16, *pycat16, *pcw16;
    cudaGetSymbolAddress((void**)&pxT16,   g_xT16);
    cudaGetSymbolAddress((void**)&pinw16,  g_inw16);
    cudaGetSymbolAddress((void**)&pxch16,  g_xch16);
    cudaGetSymbolAddress((void**)&pxpw16,  g_xpw16);
    cudaGetSymbolAddress((void**)&pgate16, g_gate16);
    cudaGetSymbolAddress((void**)&poutw16, g_outw16);
    cudaGetSymbolAddress((void**)&pycat16, g_ycat16);
    cudaGetSymbolAddress((void**)&pcw16,   g_cw16);

    static bool attr_set = false;
    if (!attr_set) {
        cudaFuncSetAttribute(hmma16, cudaFuncAttributeMaxDynamicSharedMemorySize, HMMA16_SMEM);
        attr_set = true;
    }

    const long INW  = (long)(2*DI) * DM;   // 589824
    const long OUTW = (long)DM * DI;       // 294912
    const long CWN  = (long)(2*DM) * (2*DM);

    // 0) transpose x -> fp16; weights -> fp16
    transpose_x<<<dim3(LL/32, DM/32, NB), 256>>>(x);
    convert16<<<(unsigned)((INW/2 + 255)/256), 256>>>(f_in_w, pinw16, (int)(INW/2));
    convert16<<<(unsigned)((INW/2 + 255)/256), 256>>>(b_in_w, pinw16 + INW, (int)(INW/2));
    convert16<<<(unsigned)((OUTW/2 + 255)/256), 256>>>(f_out_w, poutw16, (int)(OUTW/2));
    convert16<<<(unsigned)((OUTW/2 + 255)/256), 256>>>(b_out_w, poutw16 + OUTW, (int)(OUTW/2));
    convert16<<<(unsigned)((CWN/2 + 255)/256), 256>>>(c_w, pcw16, (int)(CWN/2));
    pad_xprojw<<<(unsigned)((2*64*DI + 255)/256), 256>>>(f_xproj, b_xproj);

    // 1) in-projection: z=dir*2+b, M=4096, N=1536, K=384 -> fp32 g_xz
    hmma16<<<dim3(24, 32, 4), 256, HMMA16_SMEM>>>(
        pxT16, DM, (long)LL*DM,
        pinw16, pinw16 + INW, nullptr,
        pxz, nullptr, 2*DI, (long)LL*2*DI, DM, 2*DI, 0);

    // 2) depthwise causal conv + silu (fp32 + fp16)
    {
        long total = (long)2 * NB * LL * DI;
        conv_silu_kernel<<<(unsigned)((total + 255) / 256), 256>>>(f_conv_w, f_conv_b, b_conv_w, b_conv_b);
    }

    // 3) x-projection (HMMA): z=dir, M=8192, N=64(pad), K=768 -> fp32 g_xdbl (56 cols)
    hmma16<<<dim3(1, 64, 2), 256, HMMA16_SMEM>>>(
        pxch16, DI, (long)NB*LL*DI,
        pxpw16, pxpw16 + 64*DI, nullptr,
        pxdbl, nullptr, XW, (long)NB*LL*XW, DI, XW, 1);

    // 4) delta + du; 4b) repack; 5) scan
    delta_gemm<<<dim3(DI/64, (NB*LL)/64, 2), 256>>>(f_dt_w, f_dt_b, b_dt_w, b_dt_b);
    repack_kernel<<<2048, 256>>>();
    scan_kernel<<<192, 256>>>(f_A_log, b_A_log);

    // 6) gate -> fp16
    {
        long total = (long)2 * NB * LL * DI / 4;
        gate_kernel<<<(unsigned)((total + 255) / 256), 256>>>(f_D, b_D);
    }

    // 7) out-projection: z=dir, M=8192, N=384, K=768 -> fp16 ycat col halves
    hmma16<<<dim3(6, 64, 2), 256, HMMA16_SMEM>>>(
        pgate16, DI, (long)NB*LL*DI,
        poutw16, poutw16 + OUTW, nullptr,
        nullptr, pycat16, 2*DM, (long)DM, DI, DM, 1);

    // 8) final 1x1 conv: M=8192, N=768, K=768, bias -> fp32 g_yc
    hmma16<<<dim3(12, 64, 1), 256, HMMA16_SMEM>>>(
        pycat16, 2*DM, 0L,
        pcw16, pcw16, c_b,
        pyc, nullptr, 2*DM, 0L, 2*DM, 2*DM, 1);

    // 9) GLU + stats + normalize
    glu_kernel<<<dim3(48, 2), 256>>>();
    stats_kernel<<<1, 32>>>();
    norm_kernel<<<dim3(LL/32, DM/32, NB), 256>>>(gn_w, gn_b, out);
}

// round 10
// speedup vs baseline: 2.0356x; 1.1570x over previous
#include <cuda_runtime.h>
#include <cuda_fp16.h>
#include <cstdint>

#define LL 4096
#define DM 384
#define DI 768
#define DS 16
#define DR 24
#define NB 2
#define XW (DR + 2*DS)   // 56

// ----------------------------- scratch (device globals) -----------------------------
__device__ float g_xz   [2][NB][LL][2*DI];   // in-proj output
__device__ float g_xc   [2][NB][LL][DI];     // after causal conv + silu (fp32)
__device__ float g_xdbl [2][NB][LL][XW];     // x-proj output (dt | B | C)
__device__ float g_delta[2][NB][LL][DI];     // softplus(dt@dtw+b)
__device__ float g_Bc   [2][NB][LL/4][DS][4];
__device__ float g_Cc   [2][NB][LL/4][DS][4];
__device__ float g_yc   [NB][LL][2*DM];
__device__ float g_glu  [NB][LL][DM];
__device__ float2 g_part[NB][64];
__device__ float2 g_stats[NB];

// fp16 operand buffers for HMMA GEMMs
__device__ __align__(16) __half g_xT16  [NB][LL][DM];
__device__ __align__(16) __half g_inw16 [2][2*DI][DM];
__device__ __align__(16) __half g_xch16 [2][NB][LL][DI];
__device__ __align__(16) __half g_xpw16 [2][64][DI];      // xproj W padded 56->64
__device__ __align__(16) __half g_gate16[2][NB][LL][DI];  // written by fused scan
__device__ __align__(16) __half g_outw16[2][DM][DI];
__device__ __align__(16) __half g_ycat16[NB][LL][2*DM];
__device__ __align__(16) __half g_cw16  [2*DM][2*DM];

// ----------------------------- helpers -----------------------------
__device__ __forceinline__ uint32_t smem_to_u32(const void* p) {
    uint32_t a;
    asm("{ .reg .u64 t; cvta.to.shared.u64 t, %1; cvt.u32.u64 %0, t; }" : "=r"(a) : "l"(p));
    return a;
}
__device__ __forceinline__ void ldsm4(uint32_t* r, uint32_t addr){
    asm volatile("ldmatrix.sync.aligned.m8n8.x4.shared.b16 {%0,%1,%2,%3}, [%4];"
        : "=r"(r[0]), "=r"(r[1]), "=r"(r[2]), "=r"(r[3]) : "r"(addr));
}
__device__ __forceinline__ void mma_f16(float* c, const uint32_t* a, const uint32_t* b){
    asm volatile("mma.sync.aligned.m16n8k16.row.col.f32.f16.f16.f32 "
        "{%0,%1,%2,%3}, {%4,%5,%6,%7}, {%8,%9}, {%0,%1,%2,%3};"
        : "+f"(c[0]), "+f"(c[1]), "+f"(c[2]), "+f"(c[3])
        : "r"(a[0]), "r"(a[1]), "r"(a[2]), "r"(a[3]), "r"(b[0]), "r"(b[1]));
}
__device__ __forceinline__ void cpasync16(uint32_t s, const void* g){
    asm volatile("cp.async.cg.shared.global [%0], [%1], 16;" :: "r"(s), "l"(g));
}
#define CP_COMMIT() asm volatile("cp.async.commit_group;" ::: "memory")
template<int N> __device__ __forceinline__ void cpwait(){
    asm volatile("cp.async.wait_group %0;" :: "n"(N) : "memory");
}

// ===========================================================================
// fp16 HMMA GEMM: tile 128x64, K-chunk 64, 4-stage cp.async pipeline.
// ===========================================================================
#define SMF_W 16384u
#define SMF_STAGE 24576u
#define HMMA16_SMEM (4 * SMF_STAGE)   // 98304

__device__ __forceinline__ void load_chunk16(
    uint32_t bufb, const __half* __restrict__ A, const __half* __restrict__ W,
    int lda, int ldw, int k0, int row0, int col0, int rev, int tid)
{
    #pragma unroll
    for (int i = 0; i < 4; i++) {
        int u = i * 256 + tid;
        int rr = u >> 3, c8 = u & 7;
        int ar = rev ? (LL - 1 - (row0 + rr)) : (row0 + rr);
        uint32_t off = ((uint32_t)(rr * 128 + c8 * 16)) ^ ((uint32_t)(rr & 7) << 4);
        cpasync16(bufb + off, A + (long)ar * lda + k0 + c8 * 8);
    }
    #pragma unroll
    for (int i = 0; i < 2; i++) {
        int u = i * 256 + tid;
        int rr = u >> 3, c8 = u & 7;
        uint32_t off = ((uint32_t)(rr * 128 + c8 * 16)) ^ ((uint32_t)(rr & 7) << 4);
        cpasync16(bufb + SMF_W + off, W + (long)(col0 + rr) * ldw + k0 + c8 * 8);
    }
}

__global__ __launch_bounds__(256, 2) void hmma16(
    const __half* __restrict__ A, int lda, long Az,
    const __half* __restrict__ W0, const __half* __restrict__ W1,
    const float* __restrict__ bias,
    float* __restrict__ Cf, __half* __restrict__ Ch,
    int ldc, long Cz, int K, int ncols, int mode)
{
    extern __shared__ __align__(16) char sm[];
    const uint32_t sb = smem_to_u32(sm);

    const int tid  = threadIdx.x;
    const int lane = tid & 31;
    const int warp = tid >> 5;
    const int m0w = (warp >> 1) * 32;
    const int n0w = (warp & 1) * 32;

    const int z = blockIdx.z;
    const int row0 = blockIdx.y * 128;
    const int col0 = blockIdx.x * 64;

    const __half *pA, *pW;
    int rev = 0;
    if (mode == 0) {
        pA = A + (long)(z & 1) * Az;
        rev = z >> 1;
        pW = (z >> 1) ? W1 : W0;
    } else {
        pA = A + (long)z * Az;
        pW = z ? W1 : W0;
    }

    float acc[2][4][4];
    #pragma unroll
    for (int i = 0; i < 2; i++)
        #pragma unroll
        for (int j = 0; j < 4; j++)
            #pragma unroll
            for (int q = 0; q < 4; q++) acc[i][j][q] = 0.f;

    const int lj = lane >> 3;
    const int lr = lane & 7;
    const int nc = K >> 6;

    load_chunk16(sb,             pA, pW, lda, K, 0,  row0, col0, rev, tid); CP_COMMIT();
    load_chunk16(sb + SMF_STAGE, pA, pW, lda, K, 64, row0, col0, rev, tid); CP_COMMIT();

    for (int c = 0; c < nc; c++) {
        if (c + 2 < nc) {
            load_chunk16(sb + ((c + 2) & 3) * SMF_STAGE, pA, pW, lda, K,
                         (c + 2) << 6, row0, col0, rev, tid);
            CP_COMMIT();
            cpwait<2>();
        } else if (c + 1 < nc) {
            cpwait<1>();
        } else {
            cpwait<0>();
        }
        __syncthreads();
        const uint32_t bufb = sb + (c & 3) * SMF_STAGE;
        #pragma unroll
        for (int ks = 0; ks < 4; ks++) {
            const int kb = ks * 16;
            uint32_t af[2][4], bf[2][4];
            #pragma unroll
            for (int mh = 0; mh < 2; mh++) {
                int row = m0w + mh * 16 + ((lj & 1) << 3) + lr;
                int kc  = kb + ((lj >> 1) << 3);
                uint32_t off = ((uint32_t)(row * 128 + kc * 2)) ^ ((uint32_t)(row & 7) << 4);
                ldsm4(af[mh], bufb + off);
            }
            #pragma unroll
            for (int np = 0; np < 2; np++) {
                int row = n0w + np * 16 + ((lj >> 1) << 3) + lr;
                int kc  = kb + ((lj & 1) << 3);
                uint32_t off = ((uint32_t)(row * 128 + kc * 2)) ^ ((uint32_t)(row & 7) << 4);
                ldsm4(bf[np], bufb + SMF_W + off);
            }
            #pragma unroll
            for (int mh = 0; mh < 2; mh++) {
                #pragma unroll
                for (int ng = 0; ng < 4; ng++)
                    mma_f16(acc[mh][ng], af[mh], &bf[ng >> 1][(ng & 1) * 2]);
            }
        }
    }

    // ---- epilogue ----
    const int g = lane >> 2, tig = lane & 3;
    if (Ch) {
        __half* Cb = Ch + (long)z * Cz;
        #pragma unroll
        for (int mh = 0; mh < 2; mh++) {
            #pragma unroll
            for (int ng = 0; ng < 4; ng++) {
                int row = row0 + m0w + mh * 16 + g;
                int col = col0 + n0w + ng * 8 + tig * 2;
                if (col < ncols) {
                    *(__half2*)&Cb[(long)row * ldc + col] =
                        __floats2half2_rn(acc[mh][ng][0], acc[mh][ng][1]);
                    *(__half2*)&Cb[(long)(row + 8) * ldc + col] =
                        __floats2half2_rn(acc[mh][ng][2], acc[mh][ng][3]);
                }
            }
        }
    } else {
        float* Cb = Cf + (long)z * Cz;
        #pragma unroll
        for (int mh = 0; mh < 2; mh++) {
            #pragma unroll
            for (int ng = 0; ng < 4; ng++) {
                int row = row0 + m0w + mh * 16 + g;
                int col = col0 + n0w + ng * 8 + tig * 2;
                if (col < ncols) {
                    float b0 = 0.f, b1 = 0.f;
                    if (bias) { b0 = bias[col]; b1 = bias[col + 1]; }
                    *(float2*)&Cb[(long)row * ldc + col] =
                        make_float2(acc[mh][ng][0] + b0, acc[mh][ng][1] + b1);
                    *(float2*)&Cb[(long)(row + 8) * ldc + col] =
                        make_float2(acc[mh][ng][2] + b0, acc[mh][ng][3] + b1);
                }
            }
        }
    }
}

// ----------------------------- fp32 -> fp16 convert (pairs) -----------------------------
__global__ __launch_bounds__(256) void convert16(
    const float* __restrict__ src, __half* __restrict__ dst, int npairs)
{
    int i = blockIdx.x * 256 + threadIdx.x;
    if (i >= npairs) return;
    float2 v = *(const float2*)&src[i * 2];
    ((__half2*)dst)[i] = __floats2half2_rn(v.x, v.y);
}

// ----------------------------- xproj weights: pad 56 -> 64 rows, fp16 -----------------------------
__global__ __launch_bounds__(256) void pad_xprojw(
    const float* __restrict__ w0, const float* __restrict__ w1)
{
    int i = blockIdx.x * 256 + threadIdx.x;
    if (i >= 2 * 64 * DI) return;
    int k = i % DI;
    int r = (i / DI) & 63;
    int dir = i / (64 * DI);
    const float* w = dir ? w1 : w0;
    float v = (r < XW) ? w[r * DI + k] : 0.f;
    g_xpw16[dir][r][k] = __float2half(v);
}

// ----------------------------- x transpose: [b][c][t] -> fp16 [b][t][c] -----------------------------
__global__ __launch_bounds__(256) void transpose_x(const float* __restrict__ x)
{
    __shared__ float s[32][33];
    const int b = blockIdx.z;
    const int t0 = blockIdx.x * 32;
    const int c0 = blockIdx.y * 32;
    const int tx = threadIdx.x & 31;
    const int ty = threadIdx.x >> 5;
    #pragma unroll
    for (int j = 0; j < 4; j++)
        s[ty + j*8][tx] = x[((long)b * DM + c0 + ty + j*8) * LL + t0 + tx];
    __syncthreads();
    #pragma unroll
    for (int j = 0; j < 4; j++)
        g_xT16[b][t0 + ty + j*8][c0 + tx] = __float2half(s[tx][ty + j*8]);
}

// ----------------------------- f32x2 helpers (delta_gemm) -----------------------------
__device__ __forceinline__ unsigned long long dup2(float x){
    unsigned long long r; asm("mov.b64 %0, {%1, %1};" : "=l"(r) : "f"(x)); return r;
}
__device__ __forceinline__ void ffma2(unsigned long long &d, unsigned long long a, unsigned long long b){
    asm("fma.rn.f32x2 %0, %1, %2, %0;" : "+l"(d) : "l"(a), "l"(b));
}
__device__ __forceinline__ float2 unpk2(unsigned long long v){
    float2 f; asm("mov.b64 {%0, %1}, %2;" : "=f"(f.x), "=f"(f.y) : "l"(v)); return f;
}

// ===========================================================================
// delta GEMM: delta = softplus(dt @ dtw^T + dtb)  (du now computed in scan)
// ===========================================================================
__global__ __launch_bounds__(256) void delta_gemm(
    const float* __restrict__ dtw0, const float* __restrict__ dtb0,
    const float* __restrict__ dtw1, const float* __restrict__ dtb1)
{
    __shared__ float As[DR][64];
    __shared__ float Bs[DR][64];
    const int dir = blockIdx.z;
    const float* Ab  = &g_xdbl[dir][0][0][0];
    float* pdl = &g_delta[dir][0][0][0];
    const float* dtw = dir ? dtw1 : dtw0;
    const float* dtb = dir ? dtb1 : dtb0;
    const int row0 = blockIdx.y * 64;
    const int col0 = blockIdx.x * 64;
    const int tid = threadIdx.x;
    const int tx = tid & 15, ty = tid >> 4;

    for (int i = tid; i < 64 * DR; i += 256) {
        int r = i / DR, k = i % DR;
        As[k][r] = Ab[(long)(row0 + r) * XW + k];
        Bs[k][r] = dtw[(long)(col0 + r) * DR + k];
    }
    __syncthreads();

    unsigned long long acc[2][4];
    #pragma unroll
    for (int i = 0; i < 2; i++)
        #pragma unroll
        for (int j = 0; j < 4; j++) acc[i][j] = 0ull;

    #pragma unroll
    for (int k = 0; k < DR; k++) {
        unsigned long long a01 = *(const unsigned long long*)&As[k][ty*4];
        unsigned long long a23 = *(const unsigned long long*)&As[k][ty*4+2];
        float4 bv = *(const float4*)&Bs[k][tx*4];
        unsigned long long b0 = dup2(bv.x), b1 = dup2(bv.y), b2 = dup2(bv.z), b3 = dup2(bv.w);
        ffma2(acc[0][0], a01, b0); ffma2(acc[0][1], a01, b1);
        ffma2(acc[0][2], a01, b2); ffma2(acc[0][3], a01, b3);
        ffma2(acc[1][0], a23, b0); ffma2(acc[1][1], a23, b1);
        ffma2(acc[1][2], a23, b2); ffma2(acc[1][3], a23, b3);
    }
    const int colb = col0 + tx*4;
    float4 bias4 = *(const float4*)&dtb[colb];
    float bsv[4] = {bias4.x, bias4.y, bias4.z, bias4.w};
    float out[4][4];
    #pragma unroll
    for (int i = 0; i < 2; i++)
        #pragma unroll
        for (int j = 0; j < 4; j++) {
            float2 f = unpk2(acc[i][j]);
            out[2*i][j] = f.x; out[2*i+1][j] = f.y;
        }
    #pragma unroll
    for (int r = 0; r < 4; r++) {
        long row = row0 + ty*4 + r;
        float dl[4];
        #pragma unroll
        for (int j = 0; j < 4; j++) {
            float s = out[r][j] + bsv[j];
            dl[j] = fmaxf(s, 0.f) + log1pf(__expf(-fabsf(s)));
        }
        *(float4*)&pdl[row * DI + colb] = make_float4(dl[0], dl[1], dl[2], dl[3]);
    }
}

// ----------------------------- B/C repack -----------------------------
__global__ __launch_bounds__(256) void repack_kernel()
{
    int id = blockIdx.x * 256 + threadIdx.x;
    if (id >= 2 * NB * LL * 2 * DS) return;
    int n = id & 15;
    int which = (id >> 4) & 1;
    int t = (id >> 5) & (LL - 1);
    int b = (id >> 17) & 1;
    int dir = (id >> 18) & 1;
    float v = g_xdbl[dir][b][t][DR + which * DS + n];
    float* dst = which ? &g_Cc[dir][b][0][0][0] : &g_Bc[dir][b][0][0][0];
    dst[(t >> 2) * (DS*4) + n * 4 + (t & 3)] = v;
}

// ----------------------------- depthwise causal conv + silu, 4 t per thread -----------------------------
__global__ __launch_bounds__(256) void conv_silu_kernel(
    const float* __restrict__ cw0, const float* __restrict__ cb0,
    const float* __restrict__ cw1, const float* __restrict__ cb1)
{
    long id = (long)blockIdx.x * 256 + threadIdx.x;
    const long total = (long)2 * NB * (LL/4) * DI;
    if (id >= total) return;
    int d = (int)(id % DI); long r = id / DI;
    int t4 = (int)(r % (LL/4)); r /= (LL/4);
    int b = (int)(r % NB); int dir = (int)(r / NB);
    const float* cw = dir ? cw1 : cw0;
    const float* cb = dir ? cb1 : cb0;
    const float* xi = &g_xz[dir][b][0][d];
    const int tb = t4 * 4;
    float rv[7];
    #pragma unroll
    for (int i = 0; i < 7; i++) {
        int tt = tb - 3 + i;
        rv[i] = (tt >= 0) ? xi[(long)tt * (2*DI)] : 0.f;
    }
    float4 w4 = *(const float4*)&cw[d * 4];
    float cbv = cb[d];
    #pragma unroll
    for (int j = 0; j < 4; j++) {
        float a = cbv + w4.x*rv[j] + w4.y*rv[j+1] + w4.z*rv[j+2] + w4.w*rv[j+3];
        float v = a / (1.f + __expf(-a));
        g_xc[dir][b][tb + j][d] = v;
        g_xch16[dir][b][tb + j][d] = __float2half(v);
    }
}

// ===========================================================================
// selective scan v2 + fused gate.
// Block = 256 threads = 16 d x 16 n for one (dir,b); 192 blocks.
// Chunks of 64 t staged in smem (coalesced); gate output staged + coalesced.
// ===========================================================================
#define SCAN_T 64
__global__ __launch_bounds__(256) void scan_kernel(
    const float* __restrict__ Al0, const float* __restrict__ Al1,
    const float* __restrict__ D0,  const float* __restrict__ D1)
{
    __shared__ float s_dl[SCAN_T][16];
    __shared__ float s_xc[SCAN_T][16];
    __shared__ float s_z [SCAN_T][16];
    __shared__ __half s_g[SCAN_T][16];

    const int bx = blockIdx.x;          // 0..191
    const int dgrp = bx % 48;
    const int b = (bx / 48) & 1;
    const int dir = bx / 96;
    const int d0 = dgrp * 16;
    const int tid = threadIdx.x;
    const int n = tid & 15;
    const int dloc = tid >> 4;
    const int d = d0 + dloc;

    const float* Al  = dir ? Al1 : Al0;
    const float* Dpt = dir ? D1 : D0;
    const float Acoef = -__expf(Al[d*DS + n]);
    const float Dv = Dpt[d];

    const float* pdl = &g_delta[dir][b][0][0];
    const float* pxc = &g_xc[dir][b][0][0];
    const float* pz  = &g_xz[dir][b][0][DI];
    const float4* pB = (const float4*)&g_Bc[dir][b][0][0][0];
    const float4* pC = (const float4*)&g_Cc[dir][b][0][0][0];
    __half* pg = &g_gate16[dir][b][0][0];

    const int l_tl = tid >> 2;          // 0..63
    const int l_c4 = (tid & 3) * 4;     // 0,4,8,12

    float h = 0.f;
    for (int t0 = 0; t0 < LL; t0 += SCAN_T) {
        __syncthreads();
        {
            long rbase = (long)(t0 + l_tl) * DI + d0 + l_c4;
            float4 vdl = *(const float4*)&pdl[rbase];
            float4 vxc = *(const float4*)&pxc[rbase];
            long rz = (long)(t0 + l_tl) * (2*DI) + d0 + l_c4;
            float4 vz = *(const float4*)&pz[rz];
            *(float4*)&s_dl[l_tl][l_c4] = vdl;
            *(float4*)&s_xc[l_tl][l_c4] = vxc;
            *(float4*)&s_z [l_tl][l_c4] = vz;
        }
        __syncthreads();
        #pragma unroll 4
        for (int t4 = 0; t4 < SCAN_T/4; t4++) {
            int tt4 = (t0 >> 2) + t4;
            float4 Bv = __ldg(&pB[tt4*16 + n]);
            float4 Cv = __ldg(&pC[tt4*16 + n]);
            #pragma unroll
            for (int j = 0; j < 4; j++) {
                int tl = t4*4 + j;
                float dl  = s_dl[tl][dloc];
                float xcv = s_xc[tl][dloc];
                float uu = dl * xcv;
                float dA = __expf(dl * Acoef);
                float Bj = (j==0)?Bv.x:(j==1)?Bv.y:(j==2)?Bv.z:Bv.w;
                float Cj = (j==0)?Cv.x:(j==1)?Cv.y:(j==2)?Cv.z:Cv.w;
                h = fmaf(dA, h, uu * Bj);
                float p = h * Cj;
                p += __shfl_xor_sync(0xffffffffu, p, 1);
                p += __shfl_xor_sync(0xffffffffu, p, 2);
                p += __shfl_xor_sync(0xffffffffu, p, 4);
                p += __shfl_xor_sync(0xffffffffu, p, 8);
                if (n == 0) {
                    float zv = s_z[tl][dloc];
                    float yv = p + xcv * Dv;
                    float gv = yv * (zv / (1.f + __expf(-zv)));
                    s_g[tl][dloc] = __float2half(gv);
                }
            }
        }
        __syncthreads();
        #pragma unroll
        for (int q = 0; q < 2; q++) {
            int u = tid + q * 256;          // 0..511 -> 64 rows x 8 half2
            int row = u >> 3, cp = u & 7;
            __half2 v = *(__half2*)&s_g[row][cp*2];
            *(__half2*)&pg[(long)(t0 + row) * DI + d0 + cp*2] = v;
        }
    }
}

// ----------------------------- GLU + partial stats -----------------------------
__global__ __launch_bounds__(256) void glu_kernel()
{
    const int batch = blockIdx.y;
    const int tid = threadIdx.x;
    float lsum = 0.f, lssq = 0.f;
    const float* yc = &g_yc[batch][0][0];
    float* gl = &g_glu[batch][0][0];
    for (int it = 0; it < 128; it++) {
        long e = (long)blockIdx.x * 32768 + (long)it * 256 + tid;
        int t = (int)(e / DM), o = (int)(e % DM);
        float a  = yc[(long)t * (2*DM) + o];
        float bg = yc[(long)t * (2*DM) + DM + o];
        float g = a * (1.f / (1.f + __expf(-bg)));
        gl[e] = g;
        lsum += g; lssq += g * g;
    }
    __shared__ float s1[256], s2[256];
    s1[tid] = lsum; s2[tid] = lssq;
    __syncthreads();
    for (int s = 128; s > 0; s >>= 1) {
        if (tid < s) { s1[tid] += s1[tid+s]; s2[tid] += s2[tid+s]; }
        __syncthreads();
    }
    if (tid == 0) g_part[batch][blockIdx.x] = make_float2(s1[0], s2[0]);
}

__global__ void stats_kernel()
{
    int b = threadIdx.x;
    if (b < NB) {
        float sum = 0.f, ssq = 0.f;
        for (int i = 0; i < 48; i++) { float2 p = g_part[b][i]; sum += p.x; ssq += p.y; }
        const float inv = 1.f / ((float)DM * (float)LL);
        float mu = sum * inv;
        float var = ssq * inv - mu * mu;
        g_stats[b] = make_float2(mu, rsqrtf(var + 1e-5f));
    }
}

// ----------------------------- normalize + transpose to output [b][c][t] -----------------------------
__global__ __launch_bounds__(256) void norm_kernel(
    const float* __restrict__ gnw, const float* __restrict__ gnb,
    float* __restrict__ out)
{
    __shared__ float s[32][33];
    const int b = blockIdx.z;
    const int t0 = blockIdx.x * 32;
    const int c0 = blockIdx.y * 32;
    const int tx = threadIdx.x & 31;
    const int ty = threadIdx.x >> 5;
    #pragma unroll
    for (int j = 0; j < 4; j++) {
        int t = t0 + ty + j*8;
        s[ty + j*8][tx] = g_glu[b][t][c0 + tx];
    }
    __syncthreads();
    float2 st = g_stats[b];
    #pragma unroll
    for (int j = 0; j < 4; j++) {
        int c = c0 + ty + j*8;
        float v = s[tx][ty + j*8];
        out[((long)b * DM + c) * LL + t0 + tx] = (v - st.x) * st.y * gnw[c] + gnb[c];
    }
}

// ----------------------------- launch -----------------------------
extern "C" void kernel_launch(void* const* d_in, const int* in_sizes, int n_in,
                              void* d_out, int out_size)
{
    (void)in_sizes; (void)n_in; (void)out_size;
    const float* x        = (const float*)d_in[0];
    const float* f_in_w   = (const float*)d_in[1];
    const float* f_conv_w = (const float*)d_in[2];
    const float* f_conv_b = (const float*)d_in[3];
    const float* f_xproj  = (const float*)d_in[4];
    const float* f_dt_w   = (const float*)d_in[5];
    const float* f_dt_b   = (const float*)d_in[6];
    const float* f_A_log  = (const float*)d_in[7];
    const float* f_D      = (const float*)d_in[8];
    const float* f_out_w  = (const float*)d_in[9];
    const float* b_in_w   = (const float*)d_in[10];
    const float* b_conv_w = (const float*)d_in[11];
    const float* b_conv_b = (const float*)d_in[12];
    const float* b_xproj  = (const float*)d_in[13];
    const float* b_dt_w   = (const float*)d_in[14];
    const float* b_dt_b   = (const float*)d_in[15];
    const float* b_A_log  = (const float*)d_in[16];
    const float* b_D      = (const float*)d_in[17];
    const float* b_out_w  = (const float*)d_in[18];
    const float* c_w      = (const float*)d_in[19];
    const float* c_b      = (const float*)d_in[20];
    const float* gn_w     = (const float*)d_in[21];
    const float* gn_b     = (const float*)d_in[22];
    float* out = (float*)d_out;

    float *pxz, *pxdbl, *pyc;
    cudaGetSymbolAddress((void**)&pxz,   g_xz);
    cudaGetSymbolAddress((void**)&pxdbl, g_xdbl);
    cudaGetSymbolAddress((void**)&pyc,   g_yc);
    __half *pxT16, *pinw16, *pxch16, *pxpw16, *pgate16, *poutw16, *pycat16, *pcw16;
    cudaGetSymbolAddress((void**)&pxT16,   g_xT16);
    cudaGetSymbolAddress((void**)&pinw16,  g_inw16);
    cudaGetSymbolAddress((void**)&pxch16,  g_xch16);
    cudaGetSymbolAddress((void**)&pxpw16,  g_xpw16);
    cudaGetSymbolAddress((void**)&pgate16, g_gate16);
    cudaGetSymbolAddress((void**)&poutw16, g_outw16);
    cudaGetSymbolAddress((void**)&pycat16, g_ycat16);
    cudaGetSymbolAddress((void**)&pcw16,   g_cw16);

    static bool attr_set = false;
    if (!attr_set) {
        cudaFuncSetAttribute(hmma16, cudaFuncAttributeMaxDynamicSharedMemorySize, HMMA16_SMEM);
        attr_set = true;
    }

    const long INW  = (long)(2*DI) * DM;
    const long OUTW = (long)DM * DI;
    const long CWN  = (long)(2*DM) * (2*DM);

    // launches 0-4: transpose + the 4 weight converts needed by inproj/outproj
    transpose_x<<<dim3(LL/32, DM/32, NB), 256>>>(x);                                   // 0
    convert16<<<(unsigned)((INW/2 + 255)/256), 256>>>(f_in_w, pinw16, (int)(INW/2));   // 1
    convert16<<<(unsigned)((INW/2 + 255)/256), 256>>>(b_in_w, pinw16 + INW, (int)(INW/2)); // 2
    convert16<<<(unsigned)((OUTW/2 + 255)/256), 256>>>(f_out_w, poutw16, (int)(OUTW/2));   // 3
    convert16<<<(unsigned)((OUTW/2 + 255)/256), 256>>>(b_out_w, poutw16 + OUTW, (int)(OUTW/2)); // 4

    // launch 5 (ncu -s 5 captures this): in-projection
    hmma16<<<dim3(24, 32, 4), 256, HMMA16_SMEM>>>(
        pxT16, DM, (long)LL*DM,
        pinw16, pinw16 + INW, nullptr,
        pxz, nullptr, 2*DI, (long)LL*2*DI, DM, 2*DI, 0);                               // 5

    convert16<<<(unsigned)((CWN/2 + 255)/256), 256>>>(c_w, pcw16, (int)(CWN/2));       // 6
    pad_xprojw<<<(unsigned)((2*64*DI + 255)/256), 256>>>(f_xproj, b_xproj);            // 7

    // depthwise causal conv + silu (4 t per thread)
    {
        long total = (long)2 * NB * (LL/4) * DI;
        conv_silu_kernel<<<(unsigned)((total + 255) / 256), 256>>>(f_conv_w, f_conv_b, b_conv_w, b_conv_b); // 8
    }

    // x-projection (HMMA)
    hmma16<<<dim3(1, 64, 2), 256, HMMA16_SMEM>>>(
        pxch16, DI, (long)NB*LL*DI,
        pxpw16, pxpw16 + 64*DI, nullptr,
        pxdbl, nullptr, XW, (long)NB*LL*XW, DI, XW, 1);                                // 9

    delta_gemm<<<dim3(DI/64, (NB*LL)/64, 2), 256>>>(f_dt_w, f_dt_b, b_dt_w, b_dt_b);   // 10
    repack_kernel<<<2048, 256>>>();                                                    // 11

    // fused scan + gate -> fp16 gate buffer
    scan_kernel<<<192, 256>>>(f_A_log, b_A_log, f_D, b_D);                             // 12

    // out-projection
    hmma16<<<dim3(6, 64, 2), 256, HMMA16_SMEM>>>(
        pgate16, DI, (long)NB*LL*DI,
        poutw16, poutw16 + OUTW, nullptr,
        nullptr, pycat16, 2*DM, (long)DM, DI, DM, 1);                                  // 13

    // final 1x1 conv
    hmma16<<<dim3(12, 64, 1), 256, HMMA16_SMEM>>>(
        pycat16, 2*DM, 0L,
        pcw16, pcw16, c_b,
        pyc, nullptr, 2*DM, 0L, 2*DM, 2*DM, 1);                                        // 14

    glu_kernel<<<dim3(48, 2), 256>>>();                                                // 15
    stats_kernel<<<1, 32>>>();                                                         // 16
    norm_kernel<<<dim3(LL/32, DM/32, NB), 256>>>(gn_w, gn_b, out);                     // 17
}